// round 6
// baseline (speedup 1.0000x reference)
#include <cuda_runtime.h>
#include <cuda.h>
#include <cuda_bf16.h>
#include <math.h>
#include <stdint.h>

#if defined(__CUDA_ARCH__) && defined(__CUDA_ARCH_FEAT_SM103_ALL)
#define HAS_TCGEN05 1
#else
#define HAS_TCGEN05 0
#endif

#define BS 8
#define LL 4800
#define D 256
#define H 8
#define DH 32
#define ROWS (BS*LL)   // 38400
#define BSTRIDE (LL*D)

#define BM 128
#define BN 256
#define BK 64
#define A_HI 0
#define A_LO 16384
#define B_HI 32768
#define B_LO 65536
#define STAGE_BYTES 98304
// dyn smem: align pad + 2 stages + epilogue tile (128x33 fp32)
#define SMEM_DYN (1024 + 2*STAGE_BYTES + 128*33*4)

#define ATOK 32
#define GEMM_GRID 148

// mbar offsets within s_mbar
#define MB_FULL0 0
#define MB_CHK0  16
#define MB_TD0   32
#define MB_EPI0  48

// ---------------- scratch (device globals) ----------------
__device__ float g_q   [BS*LL*D];
__device__ float g_k   [BS*LL*D];
__device__ float g_v   [BS*LL*D];
__device__ float g_qp  [BS*LL*D];
__device__ float g_kp  [BS*LL*D];
__device__ float g_vp  [BS*LL*D];
__device__ float g_xmid[BS*LL*D];
__device__ float g_kv  [BS*H*DH*DH];
__device__ float g_ksum[BS*H*DH];

__device__ __align__(1024) __nv_bfloat16 g_mhi[ROWS*D],   g_mlo[ROWS*D];
__device__ __align__(1024) __nv_bfloat16 g_hhi[ROWS*2*D], g_hlo[ROWS*2*D];
__device__ __align__(1024) __nv_bfloat16 g_thi[ROWS*2*D], g_tlo[ROWS*2*D];

__device__ __align__(1024) __nv_bfloat16 g_wqh[D*D],     g_wql[D*D];
__device__ __align__(1024) __nv_bfloat16 g_wkh[D*D],     g_wkl[D*D];
__device__ __align__(1024) __nv_bfloat16 g_wvh[D*D],     g_wvl[D*D];
__device__ __align__(1024) __nv_bfloat16 g_wmh[D*D],     g_wml[D*D];
__device__ __align__(1024) __nv_bfloat16 g_w1h[2*D*2*D], g_w1l[2*D*2*D];
__device__ __align__(1024) __nv_bfloat16 g_w2h[D*2*D],   g_w2l[D*2*D];

// ---------------- helpers ----------------
__device__ __forceinline__ float phi(float x) { return x > 0.f ? x + 1.f : __expf(x); }
__device__ __forceinline__ uint32_t smem_u32(const void* p) {
    uint32_t a;
    asm("{ .reg .u64 t; cvta.to.shared.u64 t, %1; cvt.u32.u64 %0, t; }" : "=r"(a) : "l"(p));
    return a;
}
__device__ __forceinline__ void split_store(__nv_bfloat16* hi, __nv_bfloat16* lo,
                                            size_t idx, float v) {
    __nv_bfloat16 h = __float2bfloat16(v);
    hi[idx] = h;
    lo[idx] = __float2bfloat16(v - __bfloat162float(h));
}

#if HAS_TCGEN05
__device__ __forceinline__ void mbar_init(uint32_t a, uint32_t cnt) {
    asm volatile("mbarrier.init.shared.b64 [%0], %1;" :: "r"(a), "r"(cnt) : "memory");
}
__device__ __forceinline__ void mbar_arrive(uint32_t a) {
    asm volatile("mbarrier.arrive.shared.b64 _, [%0];" :: "r"(a) : "memory");
}
__device__ __forceinline__ void mbar_wait(uint32_t a, uint32_t parity) {
    asm volatile(
        "{\n\t.reg .pred P;\n"
        "W_%=:\n\t"
        "mbarrier.try_wait.parity.acquire.cta.shared::cta.b64 P, [%0], %1, 0x989680;\n\t"
        "@!P bra W_%=;\n\t}"
        :: "r"(a), "r"(parity) : "memory");
}
__device__ __forceinline__ void mbar_expect_tx(uint32_t a, uint32_t bytes) {
    asm volatile("mbarrier.arrive.expect_tx.shared.b64 _, [%0], %1;"
                 :: "r"(a), "r"(bytes) : "memory");
}
__device__ __forceinline__ void tma2d(uint32_t smem, const CUtensorMap* map,
                                      int x, int y, uint32_t mbar) {
    asm volatile(
        "cp.async.bulk.tensor.2d.shared::cta.global.tile.mbarrier::complete_tx::bytes "
        "[%0], [%1, {%2, %3}], [%4];"
        :: "r"(smem), "l"(map), "r"(x), "r"(y), "r"(mbar) : "memory");
}
__device__ __forceinline__ uint64_t make_desc(uint32_t addr) {
    const uint64_t base = (uint64_t(2) << 61) | (uint64_t(1) << 46)
                        | (uint64_t(64) << 32) | (uint64_t(1) << 16);
    return base | ((uint64_t)(addr >> 4) & 0x3FFF);
}
__device__ __forceinline__ void mma_f16_ss(uint32_t d, uint64_t a, uint64_t b,
                                           uint32_t idesc, uint32_t en) {
    asm volatile(
        "{\n\t.reg .pred p;\n\tsetp.ne.u32 p, %5, 0;\n\t"
        "tcgen05.mma.cta_group::1.kind::f16 [%0], %1, %2, %3, {%4, %4, %4, %4}, p;\n\t}"
        :: "r"(d), "l"(a), "l"(b), "r"(idesc), "r"(0u), "r"(en) : "memory");
}
__device__ __forceinline__ void tc_commit(uint32_t mbar) {
    asm volatile(
        "tcgen05.commit.cta_group::1.mbarrier::arrive::one.shared::cluster.b64 [%0];"
        :: "r"(mbar) : "memory");
}
__device__ __forceinline__ void ldtm32(uint32_t* r, uint32_t addr) {
    asm volatile(
        "tcgen05.ld.sync.aligned.32x32b.x32.b32 "
        "{%0, %1, %2, %3, %4, %5, %6, %7, "
        " %8, %9, %10, %11, %12, %13, %14, %15, "
        " %16, %17, %18, %19, %20, %21, %22, %23, "
        " %24, %25, %26, %27, %28, %29, %30, %31}, [%32];"
        : "=r"(r[0]),  "=r"(r[1]),  "=r"(r[2]),  "=r"(r[3]),
          "=r"(r[4]),  "=r"(r[5]),  "=r"(r[6]),  "=r"(r[7]),
          "=r"(r[8]),  "=r"(r[9]),  "=r"(r[10]), "=r"(r[11]),
          "=r"(r[12]), "=r"(r[13]), "=r"(r[14]), "=r"(r[15]),
          "=r"(r[16]), "=r"(r[17]), "=r"(r[18]), "=r"(r[19]),
          "=r"(r[20]), "=r"(r[21]), "=r"(r[22]), "=r"(r[23]),
          "=r"(r[24]), "=r"(r[25]), "=r"(r[26]), "=r"(r[27]),
          "=r"(r[28]), "=r"(r[29]), "=r"(r[30]), "=r"(r[31])
        : "r"(addr));
    asm volatile("tcgen05.wait::ld.sync.aligned;" ::: "memory");
}
#endif

// ---------------- convert kernels ----------------
__global__ void __launch_bounds__(256) aconv(const float4* __restrict__ a,
                                             __nv_bfloat162* __restrict__ hi,
                                             __nv_bfloat162* __restrict__ lo, int n4) {
    int i = blockIdx.x * 256 + threadIdx.x;
    if (i >= n4) return;
    float4 v = a[i];
    __nv_bfloat16 h0 = __float2bfloat16(v.x), h1 = __float2bfloat16(v.y);
    __nv_bfloat16 h2 = __float2bfloat16(v.z), h3 = __float2bfloat16(v.w);
    hi[2*i]   = __halves2bfloat162(h0, h1);
    hi[2*i+1] = __halves2bfloat162(h2, h3);
    lo[2*i]   = __halves2bfloat162(__float2bfloat16(v.x - __bfloat162float(h0)),
                                   __float2bfloat16(v.y - __bfloat162float(h1)));
    lo[2*i+1] = __halves2bfloat162(__float2bfloat16(v.z - __bfloat162float(h2)),
                                   __float2bfloat16(v.w - __bfloat162float(h3)));
}

// all six weights, one launch (keeps ncu capture slot on a tc_gemm)
__global__ void __launch_bounds__(256) wconv_all(
        const float* __restrict__ Wq, const float* __restrict__ Wk,
        const float* __restrict__ Wv, const float* __restrict__ Wm,
        const float* __restrict__ W1, const float* __restrict__ W2) {
    int i = blockIdx.x * 256 + threadIdx.x;
    if (i >= 655360) return;
    const float* W; __nv_bfloat16 *hi, *lo; int K, N, li = i;
    if (li < 65536)                { W = Wq; hi = g_wqh; lo = g_wql; K = 256; N = 256; }
    else if ((li -= 65536) < 65536){ W = Wk; hi = g_wkh; lo = g_wkl; K = 256; N = 256; }
    else if ((li -= 65536) < 65536){ W = Wv; hi = g_wvh; lo = g_wvl; K = 256; N = 256; }
    else if ((li -= 65536) < 65536){ W = Wm; hi = g_wmh; lo = g_wml; K = 256; N = 256; }
    else if ((li -= 65536) < 262144){ W = W1; hi = g_w1h; lo = g_w1l; K = 512; N = 512; }
    else { li -= 262144;             W = W2; hi = g_w2h; lo = g_w2l; K = 512; N = 256; }
    int n = li / K, k = li % K;
    float v = W[(size_t)k * N + n];
    __nv_bfloat16 h = __float2bfloat16(v);
    hi[li] = h;
    lo[li] = __float2bfloat16(v - __bfloat162float(h));
}

// xb -> (copy to dst) + hcat base half (pitch 512)
__global__ void __launch_bounds__(256) prep_base(const float4* __restrict__ xb,
                                                 float4* __restrict__ dst,
                                                 __nv_bfloat16* __restrict__ hhi,
                                                 __nv_bfloat16* __restrict__ hlo) {
    int i = blockIdx.x * 256 + threadIdx.x;
    if (i >= ROWS * 64) return;
    float4 v = xb[i];
    if (dst) dst[i] = v;
    int row = i >> 6, j = i & 63;
    size_t o = (size_t)row * 512 + j * 4;
    split_store(hhi, hlo, o + 0, v.x);
    split_store(hhi, hlo, o + 1, v.y);
    split_store(hhi, hlo, o + 2, v.z);
    split_store(hhi, hlo, o + 3, v.w);
}

// ---------------- persistent warp-specialized tcgen05 GEMM ----------------
// EPI 0: fp32 -> Cf ; EPI 1: relu -> bf16 hi/lo ; EPI 2: LN -> bf16 hi/lo at coff ;
// EPI 3: Cf += 0.5*LN
template<int EPI>
__global__ void __launch_bounds__(256, 1) tc_gemm(
        const __grid_constant__ CUtensorMap mAh, const __grid_constant__ CUtensorMap mAl,
        const __grid_constant__ CUtensorMap mBh, const __grid_constant__ CUtensorMap mBl,
        const __nv_bfloat16* __restrict__ Ahi, const __nv_bfloat16* __restrict__ Alo,
        const __nv_bfloat16* __restrict__ Bhi, const __nv_bfloat16* __restrict__ Blo,
        float* __restrict__ Cf,
        __nv_bfloat16* __restrict__ Chi, __nv_bfloat16* __restrict__ Clo,
        const float* __restrict__ Gw, const float* __restrict__ Bw,
        int K, int ldc, int coff, int T, int tiles_n) {
#if HAS_TCGEN05
    extern __shared__ char dsm_raw[];
    char* sbase = (char*)(((uintptr_t)dsm_raw + 1023) & ~(uintptr_t)1023);
    char* etile = sbase + 2 * STAGE_BYTES;
    __shared__ uint32_t s_tmem;
    __shared__ __align__(8) unsigned long long s_mbar[8];
    const uint32_t mb = smem_u32(s_mbar);
    const int t = threadIdx.x;
    const int grid = gridDim.x, bid = blockIdx.x;
    const int NC = K >> 6;
    const int ntl = (bid < T) ? ((T - 1 - bid) / grid + 1) : 0;

    if ((t >> 5) == 0) {
        asm volatile("tcgen05.alloc.cta_group::1.sync.aligned.shared::cta.b32 [%0], %1;"
                     :: "r"(smem_u32(&s_tmem)), "r"(512u) : "memory");
        asm volatile("tcgen05.relinquish_alloc_permit.cta_group::1.sync.aligned;");
    }
    if (t == 0) {
        #pragma unroll
        for (int i = 0; i < 8; i++) mbar_init(mb + i * 8, 1);
        // pre-complete phase 0 of epi_done[0/1] so producer's first waits pass
        mbar_arrive(mb + MB_EPI0);
        mbar_arrive(mb + MB_EPI0 + 8);
    }
    __syncthreads();
    const uint32_t tmem = s_tmem;
    const uint32_t sb32 = smem_u32(sbase);
    const uint32_t idesc = (1u << 4) | (1u << 7) | (1u << 10)
                         | ((BN / 8) << 17) | ((BM / 16) << 24);

    // ---------------- producer: one thread of warp 7 ----------------
    if (t == 224 && ntl > 0) {
        const long total = (long)ntl * NC;
        auto issue = [&](long g) {
            int lt = (int)(g / NC), c = (int)(g % NC);
            int tile = bid + lt * grid;
            int bm = (tile / tiles_n) * BM, bn = (tile % tiles_n) * BN;
            int s = (int)(g & 1);
            uint32_t st = sb32 + s * STAGE_BYTES;
            int k0 = c * BK;
            mbar_expect_tx(mb + MB_FULL0 + s * 8, STAGE_BYTES);
            tma2d(st + A_HI, &mAh, k0, bm, mb + MB_FULL0 + s * 8);
            tma2d(st + A_LO, &mAl, k0, bm, mb + MB_FULL0 + s * 8);
            tma2d(st + B_HI, &mBh, k0, bn, mb + MB_FULL0 + s * 8);
            tma2d(st + B_LO, &mBl, k0, bn, mb + MB_FULL0 + s * 8);
        };
        issue(0);
        if (total > 1) issue(1);
        int fph[2] = {0, 0}, cph[2] = {0, 0}, eph[2] = {0, 0};
        for (int lt = 0; lt < ntl; lt++) {
            const int tp = lt & 1;
            mbar_wait(mb + MB_EPI0 + tp * 8, eph[tp]); eph[tp] ^= 1;
            asm volatile("tcgen05.fence::after_thread_sync;" ::: "memory");
            const uint32_t acc = tmem + tp * 256;
            for (int c = 0; c < NC; c++) {
                long g = (long)lt * NC + c;
                int s = (int)(g & 1);
                mbar_wait(mb + MB_FULL0 + s * 8, fph[s]); fph[s] ^= 1;
                uint32_t st = sb32 + s * STAGE_BYTES;
                uint64_t dAh = make_desc(st + A_HI), dAl = make_desc(st + A_LO);
                uint64_t dBh = make_desc(st + B_HI), dBl = make_desc(st + B_LO);
                #pragma unroll
                for (int k = 0; k < 4; k++) {
                    mma_f16_ss(acc, dAh + k * 2, dBh + k * 2, idesc, (c > 0) || (k > 0));
                    mma_f16_ss(acc, dAh + k * 2, dBl + k * 2, idesc, 1u);
                    mma_f16_ss(acc, dAl + k * 2, dBh + k * 2, idesc, 1u);
                }
                tc_commit(mb + MB_CHK0 + s * 8);
                long g2 = g + 2;
                if (g2 < total) {
                    mbar_wait(mb + MB_CHK0 + s * 8, cph[s]); cph[s] ^= 1;
                    issue(g2);
                }
            }
            tc_commit(mb + MB_TD0 + tp * 8);
        }
    }

    // ---------------- epilogue: warps 0-3 ----------------
    if (t < 128 && ntl > 0) {
        float (*tile)[33] = (float(*)[33])etile;
        int tdp[2] = {0, 0};
        for (int lt = 0; lt < ntl; lt++) {
            const int tp = lt & 1;
            const int tilei = bid + lt * grid;
            const int bm = (tilei / tiles_n) * BM, bn = (tilei % tiles_n) * BN;
            mbar_wait(mb + MB_TD0 + tp * 8, tdp[tp]); tdp[tp] ^= 1;
            asm volatile("tcgen05.fence::after_thread_sync;" ::: "memory");
            const uint32_t acc = tmem + tp * 256;
            float mean = 0.f, rstd = 0.f;
            if (EPI >= 2) {
                float s = 0.f, s2 = 0.f;
                #pragma unroll
                for (int ch = 0; ch < 8; ch++) {
                    uint32_t r[32];
                    ldtm32(r, acc + ch * 32);
                    #pragma unroll
                    for (int j = 0; j < 32; j++) {
                        float v = __uint_as_float(r[j]);
                        s += v; s2 += v * v;
                    }
                }
                mean = s * (1.f / 256.f);
                float var = fmaf(-mean, mean, s2 * (1.f / 256.f));
                rstd = rsqrtf(var + 1e-5f);
            }
            #pragma unroll
            for (int ch = 0; ch < 8; ch++) {
                uint32_t r[32];
                ldtm32(r, acc + ch * 32);
                #pragma unroll
                for (int j = 0; j < 32; j++) {
                    float v = __uint_as_float(r[j]);
                    if (EPI == 1) v = fmaxf(v, 0.f);
                    if (EPI >= 2) {
                        int col = ch * 32 + j;
                        v = (v - mean) * rstd * Gw[col] + Bw[col];
                        if (EPI == 3) v *= 0.5f;
                    }
                    tile[t][j] = v;
                }
                asm volatile("bar.sync 1, 128;" ::: "memory");
                #pragma unroll
                for (int i = 0; i < 32; i++) {
                    int idx = i * 128 + t;
                    int rr = idx >> 5, cc = idx & 31;
                    float v = tile[rr][cc];
                    size_t ro = (size_t)(bm + rr) * ldc + bn + coff + ch * 32 + cc;
                    if (EPI == 0)       Cf[ro] = v;
                    else if (EPI == 3)  Cf[ro] += v;
                    else                split_store(Chi, Clo, ro, v);
                }
                asm volatile("bar.sync 1, 128;" ::: "memory");
            }
            asm volatile("tcgen05.fence::before_thread_sync;" ::: "memory");
            asm volatile("bar.sync 1, 128;" ::: "memory");
            if (t == 0) mbar_arrive(mb + MB_EPI0 + tp * 8);
        }
    }

    __syncthreads();
    if ((t >> 5) == 0)
        asm volatile("tcgen05.dealloc.cta_group::1.sync.aligned.b32 %0, %1;"
                     :: "r"(tmem), "r"(512u));
#else
    // compile-only fallback (never runs on GB300)
    for (int tile = blockIdx.x; tile < T; tile += gridDim.x) {
        const int bm = (tile / tiles_n) * BM, bn = (tile % tiles_n) * BN;
        const int t = threadIdx.x;
        if (t < BM) {
            int row = bm + t;
            float vals[BN];
            for (int c = 0; c < BN; c++) {
                const __nv_bfloat16* ah = Ahi + (size_t)row * K;
                const __nv_bfloat16* al = Alo + (size_t)row * K;
                const __nv_bfloat16* bh = Bhi + (size_t)(bn + c) * K;
                const __nv_bfloat16* bl = Blo + (size_t)(bn + c) * K;
                float acc = 0.f;
                for (int kk = 0; kk < K; kk++)
                    acc += (__bfloat162float(ah[kk]) + __bfloat162float(al[kk])) *
                           (__bfloat162float(bh[kk]) + __bfloat162float(bl[kk]));
                vals[c] = acc;
            }
            float mean = 0.f, rstd = 1.f;
            if (EPI >= 2) {
                float s = 0.f, s2 = 0.f;
                for (int c = 0; c < BN; c++) { s += vals[c]; s2 += vals[c] * vals[c]; }
                mean = s / BN;
                rstd = rsqrtf(s2 / BN - mean * mean + 1e-5f);
            }
            for (int c = 0; c < BN; c++) {
                float v = vals[c];
                if (EPI == 1) v = fmaxf(v, 0.f);
                if (EPI >= 2) { v = (v - mean) * rstd * Gw[c] + Bw[c]; if (EPI == 3) v *= 0.5f; }
                size_t ro = (size_t)row * ldc + bn + coff + c;
                if (EPI == 0)      Cf[ro] = v;
                else if (EPI == 3) Cf[ro] += v;
                else               split_store(Chi, Clo, ro, v);
            }
        }
        __syncthreads();
    }
#endif
}

// ---------------- coalesced permutes ----------------
__global__ void __launch_bounds__(256) perm13(const float* q, const float* k, const float* v,
                                              float* qd, float* kd, float* vd) {
    __shared__ float s[8][256];
    const float* S = blockIdx.z == 0 ? q : (blockIdx.z == 1 ? k : v);
    float* Dd = blockIdx.z == 0 ? qd : (blockIdx.z == 1 ? kd : vd);
    size_t rowbase = (size_t)blockIdx.x * 8;
    int t = threadIdx.x;
    #pragma unroll
    for (int i = 0; i < 8; i++) s[i][t] = S[(rowbase + i) * 256 + t];
    __syncthreads();
    int c0 = (t & 7) * 32 + (t >> 3);
    #pragma unroll
    for (int i = 0; i < 8; i++) Dd[(rowbase + i) * 256 + t] = s[i][c0];
}

__global__ void __launch_bounds__(256) perm21(const float4* q, const float4* k, const float4* v,
                                              float4* qd, float4* kd, float4* vd) {
    const float4* S = blockIdx.z == 0 ? q : (blockIdx.z == 1 ? k : v);
    float4* Dd = blockIdx.z == 0 ? qd : (blockIdx.z == 1 ? kd : vd);
    int b = blockIdx.y;
    int idx = blockIdx.x * 256 + threadIdx.x;
    int h0 = idx / 38400;
    int r2 = idx % 38400;
    int l0 = r2 >> 3, j = r2 & 7;
    size_t bo = (size_t)b * (LL * 64);
    Dd[bo + idx] = S[bo + (size_t)l0 * 64 + h0 * 8 + j];
}

__global__ void __launch_bounds__(256) perm32(const float* q, const float* k, const float* v,
                                              float* qd, float* kd, float* vd) {
    __shared__ float sm[32][33];
    const float* S = blockIdx.z == 0 ? q : (blockIdx.z == 1 ? k : v);
    float* Dd = blockIdx.z == 0 ? qd : (blockIdx.z == 1 ? kd : vd);
    int b = blockIdx.y;
    int l0b = blockIdx.x * 32;
    size_t bo = (size_t)b * BSTRIDE;
    int wr = threadIdx.x >> 5, lane = threadIdx.x & 31;
    for (int h0 = 0; h0 < H; h0++) {
        #pragma unroll
        for (int it = 0; it < 4; it++) {
            int row = wr + it * 8;
            sm[row][lane] = S[bo + (size_t)(l0b + row) * 256 + h0 * 32 + lane];
        }
        __syncthreads();
        #pragma unroll
        for (int it = 0; it < 4; it++) {
            int d0 = wr + it * 8;
            Dd[bo + (size_t)d0 * 38400 + h0 * 4800 + l0b + lane] = sm[lane][d0];
        }
        __syncthreads();
    }
}

// ---------------- KV reduce ----------------
#define KVSPLIT 10
#define KVCHUNK (LL/KVSPLIT)
__global__ void __launch_bounds__(256) kv_reduce(const float* __restrict__ k,
                                                 const float* __restrict__ v) {
    int b = blockIdx.x >> 3, h = blockIdx.x & 7;
    int sbeg = blockIdx.y * KVCHUNK;
    const float* kb = k + (size_t)b * BSTRIDE + h * DH;
    const float* vb = v + (size_t)b * BSTRIDE + h * DH;
    __shared__ float ks[8][32], vs[8][32];
    int t = threadIdx.x;
    int r = t >> 5, c = t & 31;
    float acc[4] = {0.f, 0.f, 0.f, 0.f};
    float ksacc = 0.f;
    for (int s0 = sbeg; s0 < sbeg + KVCHUNK; s0 += 8) {
        ks[r][c] = phi(kb[(size_t)(s0 + r) * D + c]);
        vs[r][c] = vb[(size_t)(s0 + r) * D + c];
        __syncthreads();
        #pragma unroll
        for (int row = 0; row < 8; row++) {
            float ve = vs[row][c];
            #pragma unroll
            for (int jj = 0; jj < 4; jj++)
                acc[jj] += ks[row][r + jj * 8] * ve;
        }
        if (t < 32) {
            #pragma unroll
            for (int row = 0; row < 8; row++) ksacc += ks[row][t];
        }
        __syncthreads();
    }
    float* kvout = g_kv + (size_t)(b * H + h) * DH * DH;
    #pragma unroll
    for (int jj = 0; jj < 4; jj++)
        atomicAdd(&kvout[(r + jj * 8) * DH + c], acc[jj]);
    if (t < 32) atomicAdd(&g_ksum[(b * H + h) * DH + t], ksacc);
}

// ---------------- attention apply (KV hoisted to registers) ----------------
__global__ void __launch_bounds__(256) attn_out(const float* __restrict__ q,
                                                __nv_bfloat16* __restrict__ mhi,
                                                __nv_bfloat16* __restrict__ mlo) {
    extern __shared__ float as_[];
    float* sKV = as_;
    float* sKs = sKV + H * DH * DH;
    float (*sQ)[256] = (float(*)[256])(sKs + H * DH);
    float* sZ = (float*)(sQ + ATOK);
    int b  = blockIdx.y;
    int l0 = blockIdx.x * ATOK;
    int t = threadIdx.x;
    const float* kvb = g_kv + (size_t)b * H * DH * DH;
    #pragma unroll
    for (int i = t; i < H * DH * DH; i += 256) sKV[i] = kvb[i];
    if (t < H * DH) sKs[t] = g_ksum[b * H * DH + t];
    const float* qb = q + (size_t)b * BSTRIDE + (size_t)l0 * D;
    #pragma unroll
    for (int i = 0; i < ATOK; i++) sQ[i][t] = phi(qb[(size_t)i * D + t]);
    __syncthreads();
    {
        int tok = t >> 3, h = t & 7;
        float z = 0.f;
        #pragma unroll
        for (int d = 0; d < DH; d++) z += sQ[tok][h * DH + d] * sKs[h * DH + d];
        sZ[tok * H + h] = 1.f / (z + 1e-6f);
    }
    __syncthreads();
    int c = t, h = c >> 5, e = c & 31;
    float kvreg[DH];
    #pragma unroll
    for (int d = 0; d < DH; d++) kvreg[d] = sKV[(h * DH + d) * DH + e];
    size_t base = (size_t)b * BSTRIDE + (size_t)l0 * D;
    #pragma unroll 4
    for (int jj = 0; jj < ATOK; jj++) {
        float dot = 0.f;
        #pragma unroll
        for (int d = 0; d < DH; d++)
            dot += sQ[jj][h * DH + d] * kvreg[d];
        split_store(mhi, mlo, base + (size_t)jj * D + c, dot * sZ[jj * H + h]);
    }
}

// ---------------- host orchestration ----------------
typedef CUresult (*EncFn)(CUtensorMap*, CUtensorMapDataType, cuuint32_t, void*,
        const cuuint64_t*, const cuuint64_t*, const cuuint32_t*, const cuuint32_t*,
        CUtensorMapInterleave, CUtensorMapSwizzle, CUtensorMapL2promotion,
        CUtensorMapFloatOOBfill);

extern "C" void kernel_launch(void* const* d_in, const int* in_sizes, int n_in,
                              void* d_out, int out_size) {
    (void)in_sizes; (void)n_in; (void)out_size;
    const float* x   = (const float*)d_in[0];
    const float* src = (const float*)d_in[1];
    const float* Wq  = (const float*)d_in[2];
    const float* Wk  = (const float*)d_in[3];
    const float* Wv  = (const float*)d_in[4];
    const float* Wm  = (const float*)d_in[5];
    const float* W1  = (const float*)d_in[6];
    const float* W2  = (const float*)d_in[7];
    const float* g1  = (const float*)d_in[8];
    const float* b1  = (const float*)d_in[9];
    const float* g2  = (const float*)d_in[10];
    const float* b2  = (const float*)d_in[11];
    float* out = (float*)d_out;

    float *q, *k, *v, *qp, *kp, *vp, *xmid, *kv, *ksum;
    cudaGetSymbolAddress((void**)&q,    g_q);
    cudaGetSymbolAddress((void**)&k,    g_k);
    cudaGetSymbolAddress((void**)&v,    g_v);
    cudaGetSymbolAddress((void**)&qp,   g_qp);
    cudaGetSymbolAddress((void**)&kp,   g_kp);
    cudaGetSymbolAddress((void**)&vp,   g_vp);
    cudaGetSymbolAddress((void**)&xmid, g_xmid);
    cudaGetSymbolAddress((void**)&kv,   g_kv);
    cudaGetSymbolAddress((void**)&ksum, g_ksum);

    __nv_bfloat16 *mhi, *mlo, *hhi, *hlo, *thi, *tlo;
    __nv_bfloat16 *wqh, *wql, *wkh, *wkl, *wvh, *wvl, *wmh, *wml, *w1h, *w1l, *w2h, *w2l;
    cudaGetSymbolAddress((void**)&mhi, g_mhi);  cudaGetSymbolAddress((void**)&mlo, g_mlo);
    cudaGetSymbolAddress((void**)&hhi, g_hhi);  cudaGetSymbolAddress((void**)&hlo, g_hlo);
    cudaGetSymbolAddress((void**)&thi, g_thi);  cudaGetSymbolAddress((void**)&tlo, g_tlo);
    cudaGetSymbolAddress((void**)&wqh, g_wqh);  cudaGetSymbolAddress((void**)&wql, g_wql);
    cudaGetSymbolAddress((void**)&wkh, g_wkh);  cudaGetSymbolAddress((void**)&wkl, g_wkl);
    cudaGetSymbolAddress((void**)&wvh, g_wvh);  cudaGetSymbolAddress((void**)&wvl, g_wvl);
    cudaGetSymbolAddress((void**)&wmh, g_wmh);  cudaGetSymbolAddress((void**)&wml, g_wml);
    cudaGetSymbolAddress((void**)&w1h, g_w1h);  cudaGetSymbolAddress((void**)&w1l, g_w1l);
    cudaGetSymbolAddress((void**)&w2h, g_w2h);  cudaGetSymbolAddress((void**)&w2l, g_w2l);

    EncFn enc = nullptr;
    {
        void* fp = nullptr;
#if CUDART_VERSION >= 12050
        cudaDriverEntryPointQueryResult qr;
        cudaGetDriverEntryPoint("cuTensorMapEncodeTiled", &fp, cudaEnableDefault, &qr);
#else
        cudaGetDriverEntryPoint("cuTensorMapEncodeTiled", &fp, cudaEnableDefault);
#endif
        enc = (EncFn)fp;
    }
    auto mk = [&](void* ptr, uint64_t k_elems, uint64_t rows, uint32_t boxrows) {
        CUtensorMap m{};
        cuuint64_t dims[2] = {k_elems, rows};
        cuuint64_t strides[1] = {k_elems * 2};
        cuuint32_t box[2] = {64, boxrows};
        cuuint32_t es[2] = {1, 1};
        enc(&m, CU_TENSOR_MAP_DATA_TYPE_BFLOAT16, 2, ptr, dims, strides, box, es,
            CU_TENSOR_MAP_INTERLEAVE_NONE, CU_TENSOR_MAP_SWIZZLE_128B,
            CU_TENSOR_MAP_L2_PROMOTION_L2_128B, CU_TENSOR_MAP_FLOAT_OOB_FILL_NONE);
        return m;
    };
    CUtensorMap tm_mhi = mk(mhi, 256, ROWS, 128), tm_mlo = mk(mlo, 256, ROWS, 128);
    CUtensorMap tm_hhi = mk(hhi, 512, ROWS, 128), tm_hlo = mk(hlo, 512, ROWS, 128);
    CUtensorMap tm_thi = mk(thi, 512, ROWS, 128), tm_tlo = mk(tlo, 512, ROWS, 128);
    CUtensorMap tm_wqh = mk(wqh, 256, 256, 256), tm_wql = mk(wql, 256, 256, 256);
    CUtensorMap tm_wkh = mk(wkh, 256, 256, 256), tm_wkl = mk(wkl, 256, 256, 256);
    CUtensorMap tm_wvh = mk(wvh, 256, 256, 256), tm_wvl = mk(wvl, 256, 256, 256);
    CUtensorMap tm_wmh = mk(wmh, 256, 256, 256), tm_wml = mk(wml, 256, 256, 256);
    CUtensorMap tm_w1h = mk(w1h, 512, 512, 256), tm_w1l = mk(w1l, 512, 512, 256);
    CUtensorMap tm_w2h = mk(w2h, 512, 256, 256), tm_w2l = mk(w2l, 512, 256, 256);

    cudaFuncSetAttribute(tc_gemm<0>, cudaFuncAttributeMaxDynamicSharedMemorySize, SMEM_DYN);
    cudaFuncSetAttribute(tc_gemm<1>, cudaFuncAttributeMaxDynamicSharedMemorySize, SMEM_DYN);
    cudaFuncSetAttribute(tc_gemm<2>, cudaFuncAttributeMaxDynamicSharedMemorySize, SMEM_DYN);
    cudaFuncSetAttribute(tc_gemm<3>, cudaFuncAttributeMaxDynamicSharedMemorySize, SMEM_DYN);
    const int ATTN_SMEM = (H*DH*DH + H*DH + ATOK*256 + ATOK*H) * 4;
    cudaFuncSetAttribute(attn_out, cudaFuncAttributeMaxDynamicSharedMemorySize, ATTN_SMEM);

    dim3 thr(256);

    wconv_all<<<2560, thr>>>(Wq, Wk, Wv, Wm, W1, W2);

    aconv<<<ROWS*D/4/256, thr>>>((const float4*)x, (__nv_bfloat162*)mhi, (__nv_bfloat162*)mlo, ROWS*D/4);
    tc_gemm<0><<<GEMM_GRID, thr, SMEM_DYN>>>(tm_mhi, tm_mlo, tm_wqh, tm_wql,
            mhi, mlo, wqh, wql, q, nullptr, nullptr, nullptr, nullptr, D, D, 0, 300, 1);
    aconv<<<ROWS*D/4/256, thr>>>((const float4*)src, (__nv_bfloat162*)mhi, (__nv_bfloat162*)mlo, ROWS*D/4);
    tc_gemm<0><<<GEMM_GRID, thr, SMEM_DYN>>>(tm_mhi, tm_mlo, tm_wkh, tm_wkl,
            mhi, mlo, wkh, wkl, k, nullptr, nullptr, nullptr, nullptr, D, D, 0, 300, 1);
    tc_gemm<0><<<GEMM_GRID, thr, SMEM_DYN>>>(tm_mhi, tm_mlo, tm_wvh, tm_wvl,
            mhi, mlo, wvh, wvl, v, nullptr, nullptr, nullptr, nullptr, D, D, 0, 300, 1);

    prep_base<<<ROWS*64/256, thr>>>((const float4*)x, (float4*)xmid, hhi, hlo);

    auto block = [&](int mode, float* accbuf) {
        const float *qq = q, *kk = k, *vv = v;
        if (mode) {
            if (mode == 13) perm13<<<dim3(ROWS/8, 1, 3), thr>>>(q, k, v, qp, kp, vp);
            if (mode == 21) perm21<<<dim3(1200, BS, 3), thr>>>((const float4*)q, (const float4*)k, (const float4*)v,
                                                               (float4*)qp, (float4*)kp, (float4*)vp);
            if (mode == 32) perm32<<<dim3(150, BS, 3), thr>>>(q, k, v, qp, kp, vp);
            qq = qp; kk = kp; vv = vp;
        }
        cudaMemsetAsync(kv,   0, (size_t)BS*H*DH*DH*sizeof(float));
        cudaMemsetAsync(ksum, 0, (size_t)BS*H*DH*sizeof(float));
        kv_reduce<<<dim3(BS*H, KVSPLIT), thr>>>(kk, vv);
        attn_out<<<dim3(LL/ATOK, BS), thr, ATTN_SMEM>>>(qq, mhi, mlo);
        tc_gemm<2><<<GEMM_GRID, thr, SMEM_DYN>>>(tm_mhi, tm_mlo, tm_wmh, tm_wml,
                mhi, mlo, wmh, wml, nullptr, hhi, hlo, g1, b1, D, 2*D, D, 300, 1);
        tc_gemm<1><<<GEMM_GRID, thr, SMEM_DYN>>>(tm_hhi, tm_hlo, tm_w1h, tm_w1l,
                hhi, hlo, w1h, w1l, nullptr, thi, tlo, nullptr, nullptr, 2*D, 2*D, 0, 600, 2);
        tc_gemm<3><<<GEMM_GRID, thr, SMEM_DYN>>>(tm_thi, tm_tlo, tm_w2h, tm_w2l,
                thi, tlo, w2h, w2l, accbuf, nullptr, nullptr, g2, b2, 2*D, D, 0, 300, 1);
    };

    block(0,  xmid);
    block(13, xmid);
    prep_base<<<ROWS*64/256, thr>>>((const float4*)xmid, (float4*)out, hhi, hlo);
    block(21, out);
    block(32, out);
}

// round 7
// speedup vs baseline: 1.2427x; 1.2427x over previous
#include <cuda_runtime.h>
#include <cuda.h>
#include <cuda_bf16.h>
#include <math.h>
#include <stdint.h>

#if defined(__CUDA_ARCH__) && defined(__CUDA_ARCH_FEAT_SM103_ALL)
#define HAS_TCGEN05 1
#else
#define HAS_TCGEN05 0
#endif

#define BS 8
#define LL 4800
#define D 256
#define H 8
#define DH 32
#define ROWS (BS*LL)   // 38400
#define BSTRIDE (LL*D)

#define BM 128
#define BN 256
#define BK 64
#define A_HI 0
#define A_LO 16384
#define B_HI 32768
#define B_LO 65536
#define STAGE_BYTES 98304
#define SMEM_DYN (2*STAGE_BYTES + 1024)

#define ATOK 32
#define GEMM_GRID 148

// ---------------- scratch (device globals) ----------------
__device__ float g_q   [BS*LL*D];
__device__ float g_k   [BS*LL*D];
__device__ float g_v   [BS*LL*D];
__device__ float g_xmid[BS*LL*D];
__device__ float g_kvz [BS*H*DH*DH + BS*H*DH];   // kv | ksum (one memset)

__device__ __align__(1024) __nv_bfloat16 g_mhi[ROWS*D],   g_mlo[ROWS*D];
__device__ __align__(1024) __nv_bfloat16 g_hhi[ROWS*2*D], g_hlo[ROWS*2*D];
__device__ __align__(1024) __nv_bfloat16 g_thi[ROWS*2*D], g_tlo[ROWS*2*D];

__device__ __align__(1024) __nv_bfloat16 g_wqh[D*D],     g_wql[D*D];
__device__ __align__(1024) __nv_bfloat16 g_wkh[D*D],     g_wkl[D*D];
__device__ __align__(1024) __nv_bfloat16 g_wvh[D*D],     g_wvl[D*D];
__device__ __align__(1024) __nv_bfloat16 g_wmh[D*D],     g_wml[D*D];
__device__ __align__(1024) __nv_bfloat16 g_w1h[2*D*2*D], g_w1l[2*D*2*D];
__device__ __align__(1024) __nv_bfloat16 g_w2h[D*2*D],   g_w2l[D*2*D];

// ---------------- helpers ----------------
__device__ __forceinline__ float phi(float x) { return x > 0.f ? x + 1.f : __expf(x); }
__device__ __forceinline__ uint32_t smem_u32(const void* p) {
    uint32_t a;
    asm("{ .reg .u64 t; cvta.to.shared.u64 t, %1; cvt.u32.u64 %0, t; }" : "=r"(a) : "l"(p));
    return a;
}
__device__ __forceinline__ void split_store(__nv_bfloat16* hi, __nv_bfloat16* lo,
                                            size_t idx, float v) {
    __nv_bfloat16 h = __float2bfloat16(v);
    hi[idx] = h;
    lo[idx] = __float2bfloat16(v - __bfloat162float(h));
}

// permuted-view index map: element (l, c) of the MODE view -> offset in original [LL, 256]
template<int MODE>
__device__ __forceinline__ int map_off(int l, int c) {
    if (MODE == 0)  return l * 256 + c;
    if (MODE == 13) return l * 256 + ((c & 7) * 32 + (c >> 3));
    if (MODE == 21) {
        int F = l * 256 + c;
        int h0 = F / 153600;          // LL*DH
        int rem = F - h0 * 153600;
        int l0 = rem >> 5;
        return l0 * 256 + h0 * 32 + (rem & 31);
    }
    // MODE == 32
    int F = l * 256 + c;
    int d0 = F / 38400;               // H*LL
    int rem = F - d0 * 38400;
    int h0 = rem / 4800;
    int l0 = rem - h0 * 4800;
    return l0 * 256 + h0 * 32 + d0;
}

#if HAS_TCGEN05
__device__ __forceinline__ void mbar_init(uint32_t a, uint32_t cnt) {
    asm volatile("mbarrier.init.shared.b64 [%0], %1;" :: "r"(a), "r"(cnt) : "memory");
}
__device__ __forceinline__ void mbar_wait(uint32_t a, uint32_t parity) {
    asm volatile(
        "{\n\t.reg .pred P;\n"
        "W_%=:\n\t"
        "mbarrier.try_wait.parity.acquire.cta.shared::cta.b64 P, [%0], %1, 0x989680;\n\t"
        "@!P bra W_%=;\n\t}"
        :: "r"(a), "r"(parity) : "memory");
}
__device__ __forceinline__ void mbar_expect_tx(uint32_t a, uint32_t bytes) {
    asm volatile("mbarrier.arrive.expect_tx.shared.b64 _, [%0], %1;"
                 :: "r"(a), "r"(bytes) : "memory");
}
__device__ __forceinline__ void tma2d(uint32_t smem, const CUtensorMap* map,
                                      int x, int y, uint32_t mbar) {
    asm volatile(
        "cp.async.bulk.tensor.2d.shared::cta.global.tile.mbarrier::complete_tx::bytes "
        "[%0], [%1, {%2, %3}], [%4];"
        :: "r"(smem), "l"(map), "r"(x), "r"(y), "r"(mbar) : "memory");
}
__device__ __forceinline__ uint64_t make_desc(uint32_t addr) {
    const uint64_t base = (uint64_t(2) << 61) | (uint64_t(1) << 46)
                        | (uint64_t(64) << 32) | (uint64_t(1) << 16);
    return base | ((uint64_t)(addr >> 4) & 0x3FFF);
}
__device__ __forceinline__ void mma_f16_ss(uint32_t d, uint64_t a, uint64_t b,
                                           uint32_t idesc, uint32_t en) {
    asm volatile(
        "{\n\t.reg .pred p;\n\tsetp.ne.u32 p, %5, 0;\n\t"
        "tcgen05.mma.cta_group::1.kind::f16 [%0], %1, %2, %3, {%4, %4, %4, %4}, p;\n\t}"
        :: "r"(d), "l"(a), "l"(b), "r"(idesc), "r"(0u), "r"(en) : "memory");
}
__device__ __forceinline__ void tc_commit(uint32_t mbar) {
    asm volatile(
        "tcgen05.commit.cta_group::1.mbarrier::arrive::one.shared::cluster.b64 [%0];"
        :: "r"(mbar) : "memory");
}
__device__ __forceinline__ void ldtm32(uint32_t* r, uint32_t addr) {
    asm volatile(
        "tcgen05.ld.sync.aligned.32x32b.x32.b32 "
        "{%0, %1, %2, %3, %4, %5, %6, %7, "
        " %8, %9, %10, %11, %12, %13, %14, %15, "
        " %16, %17, %18, %19, %20, %21, %22, %23, "
        " %24, %25, %26, %27, %28, %29, %30, %31}, [%32];"
        : "=r"(r[0]),  "=r"(r[1]),  "=r"(r[2]),  "=r"(r[3]),
          "=r"(r[4]),  "=r"(r[5]),  "=r"(r[6]),  "=r"(r[7]),
          "=r"(r[8]),  "=r"(r[9]),  "=r"(r[10]), "=r"(r[11]),
          "=r"(r[12]), "=r"(r[13]), "=r"(r[14]), "=r"(r[15]),
          "=r"(r[16]), "=r"(r[17]), "=r"(r[18]), "=r"(r[19]),
          "=r"(r[20]), "=r"(r[21]), "=r"(r[22]), "=r"(r[23]),
          "=r"(r[24]), "=r"(r[25]), "=r"(r[26]), "=r"(r[27]),
          "=r"(r[28]), "=r"(r[29]), "=r"(r[30]), "=r"(r[31])
        : "r"(addr));
    asm volatile("tcgen05.wait::ld.sync.aligned;" ::: "memory");
}
#endif

// ---------------- convert kernels ----------------
__global__ void __launch_bounds__(256) aconv(const float4* __restrict__ a,
                                             __nv_bfloat162* __restrict__ hi,
                                             __nv_bfloat162* __restrict__ lo, int n4) {
    int i = blockIdx.x * 256 + threadIdx.x;
    if (i >= n4) return;
    float4 v = a[i];
    __nv_bfloat16 h0 = __float2bfloat16(v.x), h1 = __float2bfloat16(v.y);
    __nv_bfloat16 h2 = __float2bfloat16(v.z), h3 = __float2bfloat16(v.w);
    hi[2*i]   = __halves2bfloat162(h0, h1);
    hi[2*i+1] = __halves2bfloat162(h2, h3);
    lo[2*i]   = __halves2bfloat162(__float2bfloat16(v.x - __bfloat162float(h0)),
                                   __float2bfloat16(v.y - __bfloat162float(h1)));
    lo[2*i+1] = __halves2bfloat162(__float2bfloat16(v.z - __bfloat162float(h2)),
                                   __float2bfloat16(v.w - __bfloat162float(h3)));
}

__global__ void __launch_bounds__(256) wconv_all(
        const float* __restrict__ Wq, const float* __restrict__ Wk,
        const float* __restrict__ Wv, const float* __restrict__ Wm,
        const float* __restrict__ W1, const float* __restrict__ W2) {
    int i = blockIdx.x * 256 + threadIdx.x;
    if (i >= 655360) return;
    const float* W; __nv_bfloat16 *hi, *lo; int K, N, li = i;
    if (li < 65536)                { W = Wq; hi = g_wqh; lo = g_wql; K = 256; N = 256; }
    else if ((li -= 65536) < 65536){ W = Wk; hi = g_wkh; lo = g_wkl; K = 256; N = 256; }
    else if ((li -= 65536) < 65536){ W = Wv; hi = g_wvh; lo = g_wvl; K = 256; N = 256; }
    else if ((li -= 65536) < 65536){ W = Wm; hi = g_wmh; lo = g_wml; K = 256; N = 256; }
    else if ((li -= 65536) < 262144){ W = W1; hi = g_w1h; lo = g_w1l; K = 512; N = 512; }
    else { li -= 262144;             W = W2; hi = g_w2h; lo = g_w2l; K = 512; N = 256; }
    int n = li / K, k = li % K;
    float v = W[(size_t)k * N + n];
    __nv_bfloat16 h = __float2bfloat16(v);
    hi[li] = h;
    lo[li] = __float2bfloat16(v - __bfloat162float(h));
}

// xb -> (copy to dst) + hcat base half (pitch 512)
__global__ void __launch_bounds__(256) prep_base(const float4* __restrict__ xb,
                                                 float4* __restrict__ dst,
                                                 __nv_bfloat16* __restrict__ hhi,
                                                 __nv_bfloat16* __restrict__ hlo) {
    int i = blockIdx.x * 256 + threadIdx.x;
    if (i >= ROWS * 64) return;
    float4 v = xb[i];
    if (dst) dst[i] = v;
    int row = i >> 6, j = i & 63;
    size_t o = (size_t)row * 512 + j * 4;
    split_store(hhi, hlo, o + 0, v.x);
    split_store(hhi, hlo, o + 1, v.y);
    split_store(hhi, hlo, o + 2, v.z);
    split_store(hhi, hlo, o + 3, v.w);
}

// ---------------- tcgen05 GEMM (R5 pipeline + per-CTA tile loop) ----------------
// EPI 0: fp32 -> Cf ; EPI 1: relu -> bf16 hi/lo ; EPI 2: LN -> bf16 hi/lo at coff ;
// EPI 3: Cf += 0.5*LN
template<int EPI>
__global__ void __launch_bounds__(256, 1) tc_gemm(
        const __grid_constant__ CUtensorMap mAh, const __grid_constant__ CUtensorMap mAl,
        const __grid_constant__ CUtensorMap mBh, const __grid_constant__ CUtensorMap mBl,
        const __nv_bfloat16* __restrict__ Ahi, const __nv_bfloat16* __restrict__ Alo,
        const __nv_bfloat16* __restrict__ Bhi, const __nv_bfloat16* __restrict__ Blo,
        float* __restrict__ Cf,
        __nv_bfloat16* __restrict__ Chi, __nv_bfloat16* __restrict__ Clo,
        const float* __restrict__ Gw, const float* __restrict__ Bw,
        int K, int ldc, int coff, int T, int tiles_n) {
#if HAS_TCGEN05
    extern __shared__ char dsm_raw[];
    char* sbase = (char*)(((uintptr_t)dsm_raw + 1023) & ~(uintptr_t)1023);
    __shared__ uint32_t s_tmem;
    __shared__ __align__(8) unsigned long long s_mbar[4];  // full0 full1 chk0 chk1
    const uint32_t mb = smem_u32(s_mbar);
    const int t = threadIdx.x, wid = t >> 5, lane = t & 31;
    const int NC = K >> 6;

    if (wid == 0) {
        asm volatile("tcgen05.alloc.cta_group::1.sync.aligned.shared::cta.b32 [%0], %1;"
                     :: "r"(smem_u32(&s_tmem)), "r"(256u) : "memory");
        asm volatile("tcgen05.relinquish_alloc_permit.cta_group::1.sync.aligned;");
    }
    if (t == 0) {
        mbar_init(mb, 1); mbar_init(mb + 8, 1);
        mbar_init(mb + 16, 1); mbar_init(mb + 24, 1);
    }
    __syncthreads();
    const uint32_t tmem = s_tmem;
    const uint32_t sb32 = smem_u32(sbase);
    const uint32_t idesc = (1u << 4) | (1u << 7) | (1u << 10)
                         | ((BN / 8) << 17) | ((BM / 16) << 24);

    int fph[2] = {0, 0}, cph[2] = {0, 0};

    for (int tilei = blockIdx.x; tilei < T; tilei += GEMM_GRID) {
        const int bm = (tilei / tiles_n) * BM, bn = (tilei % tiles_n) * BN;

        if (t == 0) {
            auto issue = [&](int c) {
                int s = c & 1;
                uint32_t st = sb32 + s * STAGE_BYTES;
                int k0 = c * BK;
                mbar_expect_tx(mb + s * 8, STAGE_BYTES);
                tma2d(st + A_HI, &mAh, k0, bm, mb + s * 8);
                tma2d(st + A_LO, &mAl, k0, bm, mb + s * 8);
                tma2d(st + B_HI, &mBh, k0, bn, mb + s * 8);
                tma2d(st + B_LO, &mBl, k0, bn, mb + s * 8);
            };
            issue(0);
            if (NC > 1) issue(1);
            int pend[2] = {0, 0};
            for (int c = 0; c < NC; c++) {
                const int s = c & 1;
                mbar_wait(mb + s * 8, fph[s]); fph[s] ^= 1;
                uint32_t st = sb32 + s * STAGE_BYTES;
                uint64_t dAh = make_desc(st + A_HI), dAl = make_desc(st + A_LO);
                uint64_t dBh = make_desc(st + B_HI), dBl = make_desc(st + B_LO);
                #pragma unroll
                for (int k = 0; k < 4; k++) {
                    mma_f16_ss(tmem, dAh + k * 2, dBh + k * 2, idesc, (c > 0) || (k > 0));
                    mma_f16_ss(tmem, dAh + k * 2, dBl + k * 2, idesc, 1u);
                    mma_f16_ss(tmem, dAl + k * 2, dBh + k * 2, idesc, 1u);
                }
                tc_commit(mb + 16 + s * 8);
                pend[s] = 1;
                if (c + 2 < NC) {
                    mbar_wait(mb + 16 + s * 8, cph[s]); cph[s] ^= 1; pend[s] = 0;
                    issue(c + 2);
                }
            }
            if (pend[0]) { mbar_wait(mb + 16, cph[0]); cph[0] ^= 1; }
            if (pend[1]) { mbar_wait(mb + 24, cph[1]); cph[1] ^= 1; }
        }
        __syncthreads();
        asm volatile("tcgen05.fence::after_thread_sync;" ::: "memory");

        // epilogue (stage smem reused)
        float (*tile)[33] = (float(*)[33])sbase;
        float mean = 0.f, rstd = 0.f;
        if (EPI >= 2 && wid < 4) {
            float s = 0.f, s2 = 0.f;
            #pragma unroll
            for (int ch = 0; ch < 8; ch++) {
                uint32_t r[32];
                ldtm32(r, tmem + ch * 32);
                #pragma unroll
                for (int j = 0; j < 32; j++) {
                    float v = __uint_as_float(r[j]);
                    s += v; s2 += v * v;
                }
            }
            mean = s * (1.f / 256.f);
            float var = fmaf(-mean, mean, s2 * (1.f / 256.f));
            rstd = rsqrtf(var + 1e-5f);
        }
        #pragma unroll
        for (int ch = 0; ch < 8; ch++) {
            if (wid < 4) {
                uint32_t r[32];
                ldtm32(r, tmem + ch * 32);
                int rloc = wid * 32 + lane;
                #pragma unroll
                for (int j = 0; j < 32; j++) {
                    float v = __uint_as_float(r[j]);
                    if (EPI == 1) v = fmaxf(v, 0.f);
                    if (EPI >= 2) {
                        int col = ch * 32 + j;
                        v = (v - mean) * rstd * Gw[col] + Bw[col];
                        if (EPI == 3) v *= 0.5f;
                    }
                    tile[rloc][j] = v;
                }
            }
            __syncthreads();
            #pragma unroll
            for (int i = 0; i < 16; i++) {
                int idx = i * 256 + t;
                int rr = idx >> 5, cc = idx & 31;
                float v = tile[rr][cc];
                size_t ro = (size_t)(bm + rr) * ldc + bn + coff + ch * 32 + cc;
                if (EPI == 0)       Cf[ro] = v;
                else if (EPI == 3)  Cf[ro] += v;
                else                split_store(Chi, Clo, ro, v);
            }
            __syncthreads();
        }
    }
    if (wid == 0)
        asm volatile("tcgen05.dealloc.cta_group::1.sync.aligned.b32 %0, %1;"
                     :: "r"(tmem), "r"(256u));
#else
    // compile-only fallback (never runs on GB300)
    for (int tile = blockIdx.x; tile < T; tile += GEMM_GRID) {
        const int bm = (tile / tiles_n) * BM, bn = (tile % tiles_n) * BN;
        const int t = threadIdx.x;
        if (t < BM) {
            int row = bm + t;
            float vals[BN];
            for (int c = 0; c < BN; c++) {
                const __nv_bfloat16* ah = Ahi + (size_t)row * K;
                const __nv_bfloat16* al = Alo + (size_t)row * K;
                const __nv_bfloat16* bh = Bhi + (size_t)(bn + c) * K;
                const __nv_bfloat16* bl = Blo + (size_t)(bn + c) * K;
                float acc = 0.f;
                for (int kk = 0; kk < K; kk++)
                    acc += (__bfloat162float(ah[kk]) + __bfloat162float(al[kk])) *
                           (__bfloat162float(bh[kk]) + __bfloat162float(bl[kk]));
                vals[c] = acc;
            }
            float mean = 0.f, rstd = 1.f;
            if (EPI >= 2) {
                float s = 0.f, s2 = 0.f;
                for (int c = 0; c < BN; c++) { s += vals[c]; s2 += vals[c] * vals[c]; }
                mean = s / BN;
                rstd = rsqrtf(s2 / BN - mean * mean + 1e-5f);
            }
            for (int c = 0; c < BN; c++) {
                float v = vals[c];
                if (EPI == 1) v = fmaxf(v, 0.f);
                if (EPI >= 2) { v = (v - mean) * rstd * Gw[c] + Bw[c]; if (EPI == 3) v *= 0.5f; }
                size_t ro = (size_t)row * ldc + bn + coff + c;
                if (EPI == 0)      Cf[ro] = v;
                else if (EPI == 3) Cf[ro] += v;
                else               split_store(Chi, Clo, ro, v);
            }
        }
        __syncthreads();
    }
#endif
}

// ---------------- KV reduce with folded permutation ----------------
#define KVSPLIT 10
#define KVCHUNK (LL/KVSPLIT)
template<int MODE>
__global__ void __launch_bounds__(256) kv_reduce(const float* __restrict__ k,
                                                 const float* __restrict__ v) {
    int b = blockIdx.x >> 3, h = blockIdx.x & 7;
    int sbeg = blockIdx.y * KVCHUNK;
    const float* kb = k + (size_t)b * BSTRIDE;
    const float* vb = v + (size_t)b * BSTRIDE;
    __shared__ float ks[8][32], vs[8][32];
    int t = threadIdx.x;
    int r = t >> 5, c = t & 31;
    float acc[4] = {0.f, 0.f, 0.f, 0.f};
    float ksacc = 0.f;
    for (int s0 = sbeg; s0 < sbeg + KVCHUNK; s0 += 8) {
        int off = map_off<MODE>(s0 + r, h * DH + c);
        ks[r][c] = phi(kb[off]);
        vs[r][c] = vb[off];
        __syncthreads();
        #pragma unroll
        for (int row = 0; row < 8; row++) {
            float ve = vs[row][c];
            #pragma unroll
            for (int jj = 0; jj < 4; jj++)
                acc[jj] += ks[row][r + jj * 8] * ve;
        }
        if (t < 32) {
            #pragma unroll
            for (int row = 0; row < 8; row++) ksacc += ks[row][t];
        }
        __syncthreads();
    }
    float* kvout = g_kvz + (size_t)(b * H + h) * DH * DH;
    #pragma unroll
    for (int jj = 0; jj < 4; jj++)
        atomicAdd(&kvout[(r + jj * 8) * DH + c], acc[jj]);
    if (t < 32) atomicAdd(&g_kvz[BS*H*DH*DH + (b * H + h) * DH + t], ksacc);
}

// ---------------- attention apply with folded permutation ----------------
template<int MODE>
__global__ void __launch_bounds__(256) attn_out(const float* __restrict__ q,
                                                __nv_bfloat16* __restrict__ mhi,
                                                __nv_bfloat16* __restrict__ mlo) {
    extern __shared__ float as_[];
    float* sKV = as_;
    float* sKs = sKV + H * DH * DH;
    float (*sQ)[256] = (float(*)[256])(sKs + H * DH);
    float* sZ = (float*)(sQ + ATOK);
    int b  = blockIdx.y;
    int l0 = blockIdx.x * ATOK;
    int t = threadIdx.x;
    const float* kvb = g_kvz + (size_t)b * H * DH * DH;
    #pragma unroll
    for (int i = t; i < H * DH * DH; i += 256) sKV[i] = kvb[i];
    if (t < H * DH) sKs[t] = g_kvz[BS*H*DH*DH + b * H * DH + t];
    const float* qb = q + (size_t)b * BSTRIDE;
    #pragma unroll
    for (int i = 0; i < ATOK; i++) sQ[i][t] = phi(qb[map_off<MODE>(l0 + i, t)]);
    __syncthreads();
    {
        int tok = t >> 3, h = t & 7;
        float z = 0.f;
        #pragma unroll
        for (int d = 0; d < DH; d++) z += sQ[tok][h * DH + d] * sKs[h * DH + d];
        sZ[tok * H + h] = 1.f / (z + 1e-6f);
    }
    __syncthreads();
    int c = t, h = c >> 5, e = c & 31;
    float kvreg[DH];
    #pragma unroll
    for (int d = 0; d < DH; d++) kvreg[d] = sKV[(h * DH + d) * DH + e];
    size_t base = (size_t)b * BSTRIDE + (size_t)l0 * D;
    #pragma unroll 4
    for (int jj = 0; jj < ATOK; jj++) {
        float dot = 0.f;
        #pragma unroll
        for (int d = 0; d < DH; d++)
            dot += sQ[jj][h * DH + d] * kvreg[d];
        split_store(mhi, mlo, base + (size_t)jj * D + c, dot * sZ[jj * H + h]);
    }
}

// ---------------- host orchestration ----------------
typedef CUresult (*EncFn)(CUtensorMap*, CUtensorMapDataType, cuuint32_t, void*,
        const cuuint64_t*, const cuuint64_t*, const cuuint32_t*, const cuuint32_t*,
        CUtensorMapInterleave, CUtensorMapSwizzle, CUtensorMapL2promotion,
        CUtensorMapFloatOOBfill);

extern "C" void kernel_launch(void* const* d_in, const int* in_sizes, int n_in,
                              void* d_out, int out_size) {
    (void)in_sizes; (void)n_in; (void)out_size;
    const float* x   = (const float*)d_in[0];
    const float* src = (const float*)d_in[1];
    const float* Wq  = (const float*)d_in[2];
    const float* Wk  = (const float*)d_in[3];
    const float* Wv  = (const float*)d_in[4];
    const float* Wm  = (const float*)d_in[5];
    const float* W1  = (const float*)d_in[6];
    const float* W2  = (const float*)d_in[7];
    const float* g1  = (const float*)d_in[8];
    const float* b1  = (const float*)d_in[9];
    const float* g2  = (const float*)d_in[10];
    const float* b2  = (const float*)d_in[11];
    float* out = (float*)d_out;

    float *q, *k, *v, *xmid, *kvz;
    cudaGetSymbolAddress((void**)&q,    g_q);
    cudaGetSymbolAddress((void**)&k,    g_k);
    cudaGetSymbolAddress((void**)&v,    g_v);
    cudaGetSymbolAddress((void**)&xmid, g_xmid);
    cudaGetSymbolAddress((void**)&kvz,  g_kvz);

    __nv_bfloat16 *mhi, *mlo, *hhi, *hlo, *thi, *tlo;
    __nv_bfloat16 *wqh, *wql, *wkh, *wkl, *wvh, *wvl, *wmh, *wml, *w1h, *w1l, *w2h, *w2l;
    cudaGetSymbolAddress((void**)&mhi, g_mhi);  cudaGetSymbolAddress((void**)&mlo, g_mlo);
    cudaGetSymbolAddress((void**)&hhi, g_hhi);  cudaGetSymbolAddress((void**)&hlo, g_hlo);
    cudaGetSymbolAddress((void**)&thi, g_thi);  cudaGetSymbolAddress((void**)&tlo, g_tlo);
    cudaGetSymbolAddress((void**)&wqh, g_wqh);  cudaGetSymbolAddress((void**)&wql, g_wql);
    cudaGetSymbolAddress((void**)&wkh, g_wkh);  cudaGetSymbolAddress((void**)&wkl, g_wkl);
    cudaGetSymbolAddress((void**)&wvh, g_wvh);  cudaGetSymbolAddress((void**)&wvl, g_wvl);
    cudaGetSymbolAddress((void**)&wmh, g_wmh);  cudaGetSymbolAddress((void**)&wml, g_wml);
    cudaGetSymbolAddress((void**)&w1h, g_w1h);  cudaGetSymbolAddress((void**)&w1l, g_w1l);
    cudaGetSymbolAddress((void**)&w2h, g_w2h);  cudaGetSymbolAddress((void**)&w2l, g_w2l);

    EncFn enc = nullptr;
    {
        void* fp = nullptr;
#if CUDART_VERSION >= 12050
        cudaDriverEntryPointQueryResult qr;
        cudaGetDriverEntryPoint("cuTensorMapEncodeTiled", &fp, cudaEnableDefault, &qr);
#else
        cudaGetDriverEntryPoint("cuTensorMapEncodeTiled", &fp, cudaEnableDefault);
#endif
        enc = (EncFn)fp;
    }
    auto mk = [&](void* ptr, uint64_t k_elems, uint64_t rows, uint32_t boxrows) {
        CUtensorMap m{};
        cuuint64_t dims[2] = {k_elems, rows};
        cuuint64_t strides[1] = {k_elems * 2};
        cuuint32_t box[2] = {64, boxrows};
        cuuint32_t es[2] = {1, 1};
        enc(&m, CU_TENSOR_MAP_DATA_TYPE_BFLOAT16, 2, ptr, dims, strides, box, es,
            CU_TENSOR_MAP_INTERLEAVE_NONE, CU_TENSOR_MAP_SWIZZLE_128B,
            CU_TENSOR_MAP_L2_PROMOTION_L2_128B, CU_TENSOR_MAP_FLOAT_OOB_FILL_NONE);
        return m;
    };
    CUtensorMap tm_mhi = mk(mhi, 256, ROWS, 128), tm_mlo = mk(mlo, 256, ROWS, 128);
    CUtensorMap tm_hhi = mk(hhi, 512, ROWS, 128), tm_hlo = mk(hlo, 512, ROWS, 128);
    CUtensorMap tm_thi = mk(thi, 512, ROWS, 128), tm_tlo = mk(tlo, 512, ROWS, 128);
    CUtensorMap tm_wqh = mk(wqh, 256, 256, 256), tm_wql = mk(wql, 256, 256, 256);
    CUtensorMap tm_wkh = mk(wkh, 256, 256, 256), tm_wkl = mk(wkl, 256, 256, 256);
    CUtensorMap tm_wvh = mk(wvh, 256, 256, 256), tm_wvl = mk(wvl, 256, 256, 256);
    CUtensorMap tm_wmh = mk(wmh, 256, 256, 256), tm_wml = mk(wml, 256, 256, 256);
    CUtensorMap tm_w1h = mk(w1h, 512, 512, 256), tm_w1l = mk(w1l, 512, 512, 256);
    CUtensorMap tm_w2h = mk(w2h, 512, 256, 256), tm_w2l = mk(w2l, 512, 256, 256);

    cudaFuncSetAttribute(tc_gemm<0>, cudaFuncAttributeMaxDynamicSharedMemorySize, SMEM_DYN);
    cudaFuncSetAttribute(tc_gemm<1>, cudaFuncAttributeMaxDynamicSharedMemorySize, SMEM_DYN);
    cudaFuncSetAttribute(tc_gemm<2>, cudaFuncAttributeMaxDynamicSharedMemorySize, SMEM_DYN);
    cudaFuncSetAttribute(tc_gemm<3>, cudaFuncAttributeMaxDynamicSharedMemorySize, SMEM_DYN);
    const int ATTN_SMEM = (H*DH*DH + H*DH + ATOK*256 + ATOK*H) * 4;
    cudaFuncSetAttribute(attn_out<0>,  cudaFuncAttributeMaxDynamicSharedMemorySize, ATTN_SMEM);
    cudaFuncSetAttribute(attn_out<13>, cudaFuncAttributeMaxDynamicSharedMemorySize, ATTN_SMEM);
    cudaFuncSetAttribute(attn_out<21>, cudaFuncAttributeMaxDynamicSharedMemorySize, ATTN_SMEM);
    cudaFuncSetAttribute(attn_out<32>, cudaFuncAttributeMaxDynamicSharedMemorySize, ATTN_SMEM);

    dim3 thr(256);

    wconv_all<<<2560, thr>>>(Wq, Wk, Wv, Wm, W1, W2);

    aconv<<<ROWS*D/4/256, thr>>>((const float4*)x, (__nv_bfloat162*)mhi, (__nv_bfloat162*)mlo, ROWS*D/4);
    tc_gemm<0><<<GEMM_GRID, thr, SMEM_DYN>>>(tm_mhi, tm_mlo, tm_wqh, tm_wql,
            mhi, mlo, wqh, wql, q, nullptr, nullptr, nullptr, nullptr, D, D, 0, 300, 1);
    aconv<<<ROWS*D/4/256, thr>>>((const float4*)src, (__nv_bfloat162*)mhi, (__nv_bfloat162*)mlo, ROWS*D/4);
    tc_gemm<0><<<GEMM_GRID, thr, SMEM_DYN>>>(tm_mhi, tm_mlo, tm_wkh, tm_wkl,
            mhi, mlo, wkh, wkl, k, nullptr, nullptr, nullptr, nullptr, D, D, 0, 300, 1);
    tc_gemm<0><<<GEMM_GRID, thr, SMEM_DYN>>>(tm_mhi, tm_mlo, tm_wvh, tm_wvl,
            mhi, mlo, wvh, wvl, v, nullptr, nullptr, nullptr, nullptr, D, D, 0, 300, 1);

    prep_base<<<ROWS*64/256, thr>>>((const float4*)x, (float4*)xmid, hhi, hlo);

    auto block = [&](int mode, float* accbuf) {
        cudaMemsetAsync(kvz, 0, (size_t)(BS*H*DH*DH + BS*H*DH) * sizeof(float));
        switch (mode) {
        case 0:
            kv_reduce<0><<<dim3(BS*H, KVSPLIT), thr>>>(k, v);
            attn_out<0><<<dim3(LL/ATOK, BS), thr, ATTN_SMEM>>>(q, mhi, mlo);
            break;
        case 13:
            kv_reduce<13><<<dim3(BS*H, KVSPLIT), thr>>>(k, v);
            attn_out<13><<<dim3(LL/ATOK, BS), thr, ATTN_SMEM>>>(q, mhi, mlo);
            break;
        case 21:
            kv_reduce<21><<<dim3(BS*H, KVSPLIT), thr>>>(k, v);
            attn_out<21><<<dim3(LL/ATOK, BS), thr, ATTN_SMEM>>>(q, mhi, mlo);
            break;
        default:
            kv_reduce<32><<<dim3(BS*H, KVSPLIT), thr>>>(k, v);
            attn_out<32><<<dim3(LL/ATOK, BS), thr, ATTN_SMEM>>>(q, mhi, mlo);
            break;
        }
        tc_gemm<2><<<GEMM_GRID, thr, SMEM_DYN>>>(tm_mhi, tm_mlo, tm_wmh, tm_wml,
                mhi, mlo, wmh, wml, nullptr, hhi, hlo, g1, b1, D, 2*D, D, 300, 1);
        tc_gemm<1><<<GEMM_GRID, thr, SMEM_DYN>>>(tm_hhi, tm_hlo, tm_w1h, tm_w1l,
                hhi, hlo, w1h, w1l, nullptr, thi, tlo, nullptr, nullptr, 2*D, 2*D, 0, 600, 2);
        tc_gemm<3><<<GEMM_GRID, thr, SMEM_DYN>>>(tm_thi, tm_tlo, tm_w2h, tm_w2l,
                thi, tlo, w2h, w2l, accbuf, nullptr, nullptr, g2, b2, 2*D, D, 0, 300, 1);
    };

    block(0,  xmid);
    block(13, xmid);
    prep_base<<<ROWS*64/256, thr>>>((const float4*)xmid, (float4*)out, hhi, hlo);
    block(21, out);
    block(32, out);
}

// round 8
// speedup vs baseline: 1.5274x; 1.2290x over previous
#include <cuda_runtime.h>
#include <cuda.h>
#include <cuda_bf16.h>
#include <math.h>
#include <stdint.h>

#if defined(__CUDA_ARCH__) && defined(__CUDA_ARCH_FEAT_SM103_ALL)
#define HAS_TCGEN05 1
#else
#define HAS_TCGEN05 0
#endif

#define BS 8
#define LL 4800
#define D 256
#define H 8
#define DH 32
#define ROWS (BS*LL)   // 38400
#define BSTRIDE (LL*D)

#define BM 128
#define BN 256
#define BK 64
#define A_HI 0
#define A_LO 16384
#define B_HI 32768
#define B_LO 65536
#define STAGE_BYTES 98304
#define SMEM_DYN (2*STAGE_BYTES + 1024)

#define ATOK 32

// ---------------- scratch (device globals) ----------------
__device__ float g_q   [BS*LL*D];
__device__ float g_k   [BS*LL*D];
__device__ float g_v   [BS*LL*D];
__device__ float g_qp  [BS*LL*D];
__device__ float g_kp  [BS*LL*D];
__device__ float g_vp  [BS*LL*D];
__device__ float g_xmid[BS*LL*D];
__device__ float g_kvz [BS*H*DH*DH + BS*H*DH];   // kv | ksum (single memset)

__device__ __align__(1024) __nv_bfloat16 g_mhi[ROWS*D],   g_mlo[ROWS*D];
__device__ __align__(1024) __nv_bfloat16 g_hhi[ROWS*2*D], g_hlo[ROWS*2*D];
__device__ __align__(1024) __nv_bfloat16 g_thi[ROWS*2*D], g_tlo[ROWS*2*D];

__device__ __align__(1024) __nv_bfloat16 g_wqh[D*D],     g_wql[D*D];
__device__ __align__(1024) __nv_bfloat16 g_wkh[D*D],     g_wkl[D*D];
__device__ __align__(1024) __nv_bfloat16 g_wvh[D*D],     g_wvl[D*D];
__device__ __align__(1024) __nv_bfloat16 g_wmh[D*D],     g_wml[D*D];
__device__ __align__(1024) __nv_bfloat16 g_w1h[2*D*2*D], g_w1l[2*D*2*D];
__device__ __align__(1024) __nv_bfloat16 g_w2h[D*2*D],   g_w2l[D*2*D];

// ---------------- helpers ----------------
__device__ __forceinline__ float phi(float x) { return x > 0.f ? x + 1.f : __expf(x); }
__device__ __forceinline__ uint32_t smem_u32(const void* p) {
    uint32_t a;
    asm("{ .reg .u64 t; cvta.to.shared.u64 t, %1; cvt.u32.u64 %0, t; }" : "=r"(a) : "l"(p));
    return a;
}
__device__ __forceinline__ void split_store(__nv_bfloat16* hi, __nv_bfloat16* lo,
                                            size_t idx, float v) {
    __nv_bfloat16 h = __float2bfloat16(v);
    hi[idx] = h;
    lo[idx] = __float2bfloat16(v - __bfloat162float(h));
}

// index map for MODE view (0 = identity, 21 = coalesced [h,L,dh] view)
template<int MODE>
__device__ __forceinline__ int map_off(int l, int c) {
    if (MODE == 21) {
        int F = l * 256 + c;
        int h0 = F / 153600;          // LL*DH
        int rem = F - h0 * 153600;
        int l0 = rem >> 5;
        return l0 * 256 + h0 * 32 + (rem & 31);
    }
    return l * 256 + c;
}

#if HAS_TCGEN05
__device__ __forceinline__ void mbar_init(uint32_t a, uint32_t cnt) {
    asm volatile("mbarrier.init.shared.b64 [%0], %1;" :: "r"(a), "r"(cnt) : "memory");
}
__device__ __forceinline__ void mbar_wait(uint32_t a, uint32_t parity) {
    asm volatile(
        "{\n\t.reg .pred P;\n"
        "W_%=:\n\t"
        "mbarrier.try_wait.parity.acquire.cta.shared::cta.b64 P, [%0], %1, 0x989680;\n\t"
        "@!P bra W_%=;\n\t}"
        :: "r"(a), "r"(parity) : "memory");
}
__device__ __forceinline__ void mbar_expect_tx(uint32_t a, uint32_t bytes) {
    asm volatile("mbarrier.arrive.expect_tx.shared.b64 _, [%0], %1;"
                 :: "r"(a), "r"(bytes) : "memory");
}
__device__ __forceinline__ void tma2d(uint32_t smem, const CUtensorMap* map,
                                      int x, int y, uint32_t mbar) {
    asm volatile(
        "cp.async.bulk.tensor.2d.shared::cta.global.tile.mbarrier::complete_tx::bytes "
        "[%0], [%1, {%2, %3}], [%4];"
        :: "r"(smem), "l"(map), "r"(x), "r"(y), "r"(mbar) : "memory");
}
__device__ __forceinline__ uint64_t make_desc(uint32_t addr) {
    const uint64_t base = (uint64_t(2) << 61) | (uint64_t(1) << 46)
                        | (uint64_t(64) << 32) | (uint64_t(1) << 16);
    return base | ((uint64_t)(addr >> 4) & 0x3FFF);
}
__device__ __forceinline__ void mma_f16_ss(uint32_t d, uint64_t a, uint64_t b,
                                           uint32_t idesc, uint32_t en) {
    asm volatile(
        "{\n\t.reg .pred p;\n\tsetp.ne.u32 p, %5, 0;\n\t"
        "tcgen05.mma.cta_group::1.kind::f16 [%0], %1, %2, %3, {%4, %4, %4, %4}, p;\n\t}"
        :: "r"(d), "l"(a), "l"(b), "r"(idesc), "r"(0u), "r"(en) : "memory");
}
__device__ __forceinline__ void tc_commit(uint32_t mbar) {
    asm volatile(
        "tcgen05.commit.cta_group::1.mbarrier::arrive::one.shared::cluster.b64 [%0];"
        :: "r"(mbar) : "memory");
}
__device__ __forceinline__ void ldtm32(uint32_t* r, uint32_t addr) {
    asm volatile(
        "tcgen05.ld.sync.aligned.32x32b.x32.b32 "
        "{%0, %1, %2, %3, %4, %5, %6, %7, "
        " %8, %9, %10, %11, %12, %13, %14, %15, "
        " %16, %17, %18, %19, %20, %21, %22, %23, "
        " %24, %25, %26, %27, %28, %29, %30, %31}, [%32];"
        : "=r"(r[0]),  "=r"(r[1]),  "=r"(r[2]),  "=r"(r[3]),
          "=r"(r[4]),  "=r"(r[5]),  "=r"(r[6]),  "=r"(r[7]),
          "=r"(r[8]),  "=r"(r[9]),  "=r"(r[10]), "=r"(r[11]),
          "=r"(r[12]), "=r"(r[13]), "=r"(r[14]), "=r"(r[15]),
          "=r"(r[16]), "=r"(r[17]), "=r"(r[18]), "=r"(r[19]),
          "=r"(r[20]), "=r"(r[21]), "=r"(r[22]), "=r"(r[23]),
          "=r"(r[24]), "=r"(r[25]), "=r"(r[26]), "=r"(r[27]),
          "=r"(r[28]), "=r"(r[29]), "=r"(r[30]), "=r"(r[31])
        : "r"(addr));
    asm volatile("tcgen05.wait::ld.sync.aligned;" ::: "memory");
}
#endif

// ---------------- convert kernels ----------------
__global__ void __launch_bounds__(256) aconv(const float4* __restrict__ a,
                                             __nv_bfloat162* __restrict__ hi,
                                             __nv_bfloat162* __restrict__ lo, int n4) {
    int i = blockIdx.x * 256 + threadIdx.x;
    if (i >= n4) return;
    float4 v = a[i];
    __nv_bfloat16 h0 = __float2bfloat16(v.x), h1 = __float2bfloat16(v.y);
    __nv_bfloat16 h2 = __float2bfloat16(v.z), h3 = __float2bfloat16(v.w);
    hi[2*i]   = __halves2bfloat162(h0, h1);
    hi[2*i+1] = __halves2bfloat162(h2, h3);
    lo[2*i]   = __halves2bfloat162(__float2bfloat16(v.x - __bfloat162float(h0)),
                                   __float2bfloat16(v.y - __bfloat162float(h1)));
    lo[2*i+1] = __halves2bfloat162(__float2bfloat16(v.z - __bfloat162float(h2)),
                                   __float2bfloat16(v.w - __bfloat162float(h3)));
}

__global__ void __launch_bounds__(256) wconv_all(
        const float* __restrict__ Wq, const float* __restrict__ Wk,
        const float* __restrict__ Wv, const float* __restrict__ Wm,
        const float* __restrict__ W1, const float* __restrict__ W2) {
    int i = blockIdx.x * 256 + threadIdx.x;
    if (i >= 655360) return;
    const float* W; __nv_bfloat16 *hi, *lo; int K, N, li = i;
    if (li < 65536)                { W = Wq; hi = g_wqh; lo = g_wql; K = 256; N = 256; }
    else if ((li -= 65536) < 65536){ W = Wk; hi = g_wkh; lo = g_wkl; K = 256; N = 256; }
    else if ((li -= 65536) < 65536){ W = Wv; hi = g_wvh; lo = g_wvl; K = 256; N = 256; }
    else if ((li -= 65536) < 65536){ W = Wm; hi = g_wmh; lo = g_wml; K = 256; N = 256; }
    else if ((li -= 65536) < 262144){ W = W1; hi = g_w1h; lo = g_w1l; K = 512; N = 512; }
    else { li -= 262144;             W = W2; hi = g_w2h; lo = g_w2l; K = 512; N = 256; }
    int n = li / K, k = li % K;
    float v = W[(size_t)k * N + n];
    __nv_bfloat16 h = __float2bfloat16(v);
    hi[li] = h;
    lo[li] = __float2bfloat16(v - __bfloat162float(h));
}

// xb -> (copy to dst) + hcat base half (pitch 512)
__global__ void __launch_bounds__(256) prep_base(const float4* __restrict__ xb,
                                                 float4* __restrict__ dst,
                                                 __nv_bfloat16* __restrict__ hhi,
                                                 __nv_bfloat16* __restrict__ hlo) {
    int i = blockIdx.x * 256 + threadIdx.x;
    if (i >= ROWS * 64) return;
    float4 v = xb[i];
    if (dst) dst[i] = v;
    int row = i >> 6, j = i & 63;
    size_t o = (size_t)row * 512 + j * 4;
    split_store(hhi, hlo, o + 0, v.x);
    split_store(hhi, hlo, o + 1, v.y);
    split_store(hhi, hlo, o + 2, v.z);
    split_store(hhi, hlo, o + 3, v.w);
}

// ---------------- tcgen05 GEMM with TMA mainloop (R5-measured pipeline) ----------------
// EPI 0: fp32 -> Cf ; EPI 1: relu -> bf16 hi/lo ; EPI 2: LN -> bf16 hi/lo at coff ;
// EPI 3: Cf += 0.5*LN
template<int EPI>
__global__ void __launch_bounds__(256, 1) tc_gemm(
        const __grid_constant__ CUtensorMap mAh, const __grid_constant__ CUtensorMap mAl,
        const __grid_constant__ CUtensorMap mBh, const __grid_constant__ CUtensorMap mBl,
        const __nv_bfloat16* __restrict__ Ahi, const __nv_bfloat16* __restrict__ Alo,
        const __nv_bfloat16* __restrict__ Bhi, const __nv_bfloat16* __restrict__ Blo,
        float* __restrict__ Cf,
        __nv_bfloat16* __restrict__ Chi, __nv_bfloat16* __restrict__ Clo,
        const float* __restrict__ Gw, const float* __restrict__ Bw,
        int K, int ldc, int coff) {
#if HAS_TCGEN05
    extern __shared__ char dsm_raw[];
    char* sbase = (char*)(((uintptr_t)dsm_raw + 1023) & ~(uintptr_t)1023);
    __shared__ uint32_t s_tmem;
    __shared__ __align__(8) unsigned long long s_mbar[4];  // full0 full1 mma0 mma1
    const uint32_t mb = smem_u32(s_mbar);
    const int t = threadIdx.x, wid = t >> 5, lane = t & 31;

    if (wid == 0) {
        asm volatile("tcgen05.alloc.cta_group::1.sync.aligned.shared::cta.b32 [%0], %1;"
                     :: "r"(smem_u32(&s_tmem)), "r"(256u) : "memory");
        asm volatile("tcgen05.relinquish_alloc_permit.cta_group::1.sync.aligned;");
    }
    if (t == 0) {
        mbar_init(mb, 1); mbar_init(mb + 8, 1);
        mbar_init(mb + 16, 1); mbar_init(mb + 24, 1);
    }
    __syncthreads();
    const uint32_t tmem = s_tmem;

    const int bm = blockIdx.y * BM, bn = blockIdx.x * BN;
    const int NC = K >> 6;
    const uint32_t idesc = (1u << 4) | (1u << 7) | (1u << 10)
                         | ((BN / 8) << 17) | ((BM / 16) << 24);
    const uint32_t sb32 = smem_u32(sbase);

    if (t == 0) {
        mbar_expect_tx(mb, STAGE_BYTES);
        tma2d(sb32 + A_HI, &mAh, 0, bm, mb);
        tma2d(sb32 + A_LO, &mAl, 0, bm, mb);
        tma2d(sb32 + B_HI, &mBh, 0, bn, mb);
        tma2d(sb32 + B_LO, &mBl, 0, bn, mb);
        if (NC > 1) {
            uint32_t st = sb32 + STAGE_BYTES;
            mbar_expect_tx(mb + 8, STAGE_BYTES);
            tma2d(st + A_HI, &mAh, BK, bm, mb + 8);
            tma2d(st + A_LO, &mAl, BK, bm, mb + 8);
            tma2d(st + B_HI, &mBh, BK, bn, mb + 8);
            tma2d(st + B_LO, &mBl, BK, bn, mb + 8);
        }
        int fph[2] = {0, 0}, mph[2] = {0, 0}, pend[2] = {0, 0};
        for (int c = 0; c < NC; c++) {
            const int s = c & 1;
            mbar_wait(mb + s * 8, fph[s]); fph[s] ^= 1;
            uint32_t st = sb32 + s * STAGE_BYTES;
            uint64_t dAh = make_desc(st + A_HI), dAl = make_desc(st + A_LO);
            uint64_t dBh = make_desc(st + B_HI), dBl = make_desc(st + B_LO);
            #pragma unroll
            for (int k = 0; k < 4; k++) {
                mma_f16_ss(tmem, dAh + k * 2, dBh + k * 2, idesc, (c > 0) || (k > 0));
                mma_f16_ss(tmem, dAh + k * 2, dBl + k * 2, idesc, 1u);
                mma_f16_ss(tmem, dAl + k * 2, dBh + k * 2, idesc, 1u);
            }
            tc_commit(mb + 16 + s * 8);
            pend[s] = 1;
            if (c + 2 < NC) {
                mbar_wait(mb + 16 + s * 8, mph[s]); mph[s] ^= 1; pend[s] = 0;
                int k0 = (c + 2) * BK;
                mbar_expect_tx(mb + s * 8, STAGE_BYTES);
                tma2d(st + A_HI, &mAh, k0, bm, mb + s * 8);
                tma2d(st + A_LO, &mAl, k0, bm, mb + s * 8);
                tma2d(st + B_HI, &mBh, k0, bn, mb + s * 8);
                tma2d(st + B_LO, &mBl, k0, bn, mb + s * 8);
            }
        }
        if (pend[0]) mbar_wait(mb + 16, mph[0]);
        if (pend[1]) mbar_wait(mb + 24, mph[1]);
    }
    __syncthreads();
    asm volatile("tcgen05.fence::after_thread_sync;" ::: "memory");

    // epilogue: smem-staged coalesced stores
    float (*tile)[33] = (float(*)[33])sbase;
    float mean = 0.f, rstd = 0.f;
    if (EPI >= 2 && wid < 4) {
        float s = 0.f, s2 = 0.f;
        #pragma unroll
        for (int ch = 0; ch < 8; ch++) {
            uint32_t r[32];
            ldtm32(r, tmem + ch * 32);
            #pragma unroll
            for (int j = 0; j < 32; j++) {
                float v = __uint_as_float(r[j]);
                s += v; s2 += v * v;
            }
        }
        mean = s * (1.f / 256.f);
        float var = fmaf(-mean, mean, s2 * (1.f / 256.f));
        rstd = rsqrtf(var + 1e-5f);
    }
    #pragma unroll
    for (int ch = 0; ch < 8; ch++) {
        if (wid < 4) {
            uint32_t r[32];
            ldtm32(r, tmem + ch * 32);
            int rloc = wid * 32 + lane;
            #pragma unroll
            for (int j = 0; j < 32; j++) {
                float v = __uint_as_float(r[j]);
                if (EPI == 1) v = fmaxf(v, 0.f);
                if (EPI >= 2) {
                    int col = ch * 32 + j;
                    v = (v - mean) * rstd * Gw[col] + Bw[col];
                    if (EPI == 3) v *= 0.5f;
                }
                tile[rloc][j] = v;
            }
        }
        __syncthreads();
        #pragma unroll
        for (int i = 0; i < 16; i++) {
            int idx = i * 256 + t;
            int rr = idx >> 5, cc = idx & 31;
            float v = tile[rr][cc];
            size_t ro = (size_t)(bm + rr) * ldc + bn + coff + ch * 32 + cc;
            if (EPI == 0)       Cf[ro] = v;
            else if (EPI == 3)  Cf[ro] += v;
            else                split_store(Chi, Clo, ro, v);
        }
        __syncthreads();
    }
    if (wid == 0)
        asm volatile("tcgen05.dealloc.cta_group::1.sync.aligned.b32 %0, %1;"
                     :: "r"(tmem), "r"(256u));
#else
    // compile-only fallback (never runs on GB300)
    const int bm = blockIdx.y * BM, bn = blockIdx.x * BN;
    const int t = threadIdx.x;
    if (t < BM) {
        int row = bm + t;
        float vals[BN];
        for (int c = 0; c < BN; c++) {
            const __nv_bfloat16* ah = Ahi + (size_t)row * K;
            const __nv_bfloat16* al = Alo + (size_t)row * K;
            const __nv_bfloat16* bh = Bhi + (size_t)(bn + c) * K;
            const __nv_bfloat16* bl = Blo + (size_t)(bn + c) * K;
            float acc = 0.f;
            for (int kk = 0; kk < K; kk++)
                acc += (__bfloat162float(ah[kk]) + __bfloat162float(al[kk])) *
                       (__bfloat162float(bh[kk]) + __bfloat162float(bl[kk]));
            vals[c] = acc;
        }
        float mean = 0.f, rstd = 1.f;
        if (EPI >= 2) {
            float s = 0.f, s2 = 0.f;
            for (int c = 0; c < BN; c++) { s += vals[c]; s2 += vals[c] * vals[c]; }
            mean = s / BN;
            rstd = rsqrtf(s2 / BN - mean * mean + 1e-5f);
        }
        for (int c = 0; c < BN; c++) {
            float v = vals[c];
            if (EPI == 1) v = fmaxf(v, 0.f);
            if (EPI >= 2) { v = (v - mean) * rstd * Gw[c] + Bw[c]; if (EPI == 3) v *= 0.5f; }
            size_t ro = (size_t)row * ldc + bn + coff + c;
            if (EPI == 0)      Cf[ro] = v;
            else if (EPI == 3) Cf[ro] += v;
            else               split_store(Chi, Clo, ro, v);
        }
    }
#endif
}

// ---------------- coalesced permutes (modes 13 and 32 only) ----------------
__global__ void __launch_bounds__(256) perm13(const float* q, const float* k, const float* v,
                                              float* qd, float* kd, float* vd) {
    __shared__ float s[8][256];
    const float* S = blockIdx.z == 0 ? q : (blockIdx.z == 1 ? k : v);
    float* Dd = blockIdx.z == 0 ? qd : (blockIdx.z == 1 ? kd : vd);
    size_t rowbase = (size_t)blockIdx.x * 8;
    int t = threadIdx.x;
    #pragma unroll
    for (int i = 0; i < 8; i++) s[i][t] = S[(rowbase + i) * 256 + t];
    __syncthreads();
    int c0 = (t & 7) * 32 + (t >> 3);
    #pragma unroll
    for (int i = 0; i < 8; i++) Dd[(rowbase + i) * 256 + t] = s[i][c0];
}

__global__ void __launch_bounds__(256) perm32(const float* q, const float* k, const float* v,
                                              float* qd, float* kd, float* vd) {
    __shared__ float sm[32][33];
    const float* S = blockIdx.z == 0 ? q : (blockIdx.z == 1 ? k : v);
    float* Dd = blockIdx.z == 0 ? qd : (blockIdx.z == 1 ? kd : vd);
    int b = blockIdx.y;
    int l0b = blockIdx.x * 32;
    size_t bo = (size_t)b * BSTRIDE;
    int wr = threadIdx.x >> 5, lane = threadIdx.x & 31;
    for (int h0 = 0; h0 < H; h0++) {
        #pragma unroll
        for (int it = 0; it < 4; it++) {
            int row = wr + it * 8;
            sm[row][lane] = S[bo + (size_t)(l0b + row) * 256 + h0 * 32 + lane];
        }
        __syncthreads();
        #pragma unroll
        for (int it = 0; it < 4; it++) {
            int d0 = wr + it * 8;
            Dd[bo + (size_t)d0 * 38400 + h0 * 4800 + l0b + lane] = sm[lane][d0];
        }
        __syncthreads();
    }
}

// ---------------- KV reduce (MODE 0 or 21 folded) ----------------
#define KVSPLIT 10
#define KVCHUNK (LL/KVSPLIT)
template<int MODE>
__global__ void __launch_bounds__(256) kv_reduce(const float* __restrict__ k,
                                                 const float* __restrict__ v) {
    int b = blockIdx.x >> 3, h = blockIdx.x & 7;
    int sbeg = blockIdx.y * KVCHUNK;
    const float* kb = k + (size_t)b * BSTRIDE;
    const float* vb = v + (size_t)b * BSTRIDE;
    __shared__ float ks[8][32], vs[8][32];
    int t = threadIdx.x;
    int r = t >> 5, c = t & 31;
    float acc[4] = {0.f, 0.f, 0.f, 0.f};
    float ksacc = 0.f;
    for (int s0 = sbeg; s0 < sbeg + KVCHUNK; s0 += 8) {
        int off = map_off<MODE>(s0 + r, h * DH + c);
        ks[r][c] = phi(kb[off]);
        vs[r][c] = vb[off];
        __syncthreads();
        #pragma unroll
        for (int row = 0; row < 8; row++) {
            float ve = vs[row][c];
            #pragma unroll
            for (int jj = 0; jj < 4; jj++)
                acc[jj] += ks[row][r + jj * 8] * ve;
        }
        if (t < 32) {
            #pragma unroll
            for (int row = 0; row < 8; row++) ksacc += ks[row][t];
        }
        __syncthreads();
    }
    float* kvout = g_kvz + (size_t)(b * H + h) * DH * DH;
    #pragma unroll
    for (int jj = 0; jj < 4; jj++)
        atomicAdd(&kvout[(r + jj * 8) * DH + c], acc[jj]);
    if (t < 32) atomicAdd(&g_kvz[BS*H*DH*DH + (b * H + h) * DH + t], ksacc);
}

// ---------------- attention apply (MODE 0 or 21 folded; KV in registers) ----------------
template<int MODE>
__global__ void __launch_bounds__(256) attn_out(const float* __restrict__ q,
                                                __nv_bfloat16* __restrict__ mhi,
                                                __nv_bfloat16* __restrict__ mlo) {
    extern __shared__ float as_[];
    float* sKV = as_;
    float* sKs = sKV + H * DH * DH;
    float (*sQ)[256] = (float(*)[256])(sKs + H * DH);
    float* sZ = (float*)(sQ + ATOK);
    int b  = blockIdx.y;
    int l0 = blockIdx.x * ATOK;
    int t = threadIdx.x;
    const float* kvb = g_kvz + (size_t)b * H * DH * DH;
    #pragma unroll
    for (int i = t; i < H * DH * DH; i += 256) sKV[i] = kvb[i];
    if (t < H * DH) sKs[t] = g_kvz[BS*H*DH*DH + b * H * DH + t];
    const float* qb = q + (size_t)b * BSTRIDE;
    #pragma unroll
    for (int i = 0; i < ATOK; i++) sQ[i][t] = phi(qb[map_off<MODE>(l0 + i, t)]);
    __syncthreads();
    {
        int tok = t >> 3, h = t & 7;
        float z = 0.f;
        #pragma unroll
        for (int d = 0; d < DH; d++) z += sQ[tok][h * DH + d] * sKs[h * DH + d];
        sZ[tok * H + h] = 1.f / (z + 1e-6f);
    }
    __syncthreads();
    int c = t, h = c >> 5, e = c & 31;
    float kvreg[DH];
    #pragma unroll
    for (int d = 0; d < DH; d++) kvreg[d] = sKV[(h * DH + d) * DH + e];
    size_t base = (size_t)b * BSTRIDE + (size_t)l0 * D;
    #pragma unroll 4
    for (int jj = 0; jj < ATOK; jj++) {
        float dot = 0.f;
        #pragma unroll
        for (int d = 0; d < DH; d++)
            dot += sQ[jj][h * DH + d] * kvreg[d];
        split_store(mhi, mlo, base + (size_t)jj * D + c, dot * sZ[jj * H + h]);
    }
}

// ---------------- host orchestration ----------------
typedef CUresult (*EncFn)(CUtensorMap*, CUtensorMapDataType, cuuint32_t, void*,
        const cuuint64_t*, const cuuint64_t*, const cuuint32_t*, const cuuint32_t*,
        CUtensorMapInterleave, CUtensorMapSwizzle, CUtensorMapL2promotion,
        CUtensorMapFloatOOBfill);

extern "C" void kernel_launch(void* const* d_in, const int* in_sizes, int n_in,
                              void* d_out, int out_size) {
    (void)in_sizes; (void)n_in; (void)out_size;
    const float* x   = (const float*)d_in[0];
    const float* src = (const float*)d_in[1];
    const float* Wq  = (const float*)d_in[2];
    const float* Wk  = (const float*)d_in[3];
    const float* Wv  = (const float*)d_in[4];
    const float* Wm  = (const float*)d_in[5];
    const float* W1  = (const float*)d_in[6];
    const float* W2  = (const float*)d_in[7];
    const float* g1  = (const float*)d_in[8];
    const float* b1  = (const float*)d_in[9];
    const float* g2  = (const float*)d_in[10];
    const float* b2  = (const float*)d_in[11];
    float* out = (float*)d_out;

    float *q, *k, *v, *qp, *kp, *vp, *xmid, *kvz;
    cudaGetSymbolAddress((void**)&q,    g_q);
    cudaGetSymbolAddress((void**)&k,    g_k);
    cudaGetSymbolAddress((void**)&v,    g_v);
    cudaGetSymbolAddress((void**)&qp,   g_qp);
    cudaGetSymbolAddress((void**)&kp,   g_kp);
    cudaGetSymbolAddress((void**)&vp,   g_vp);
    cudaGetSymbolAddress((void**)&xmid, g_xmid);
    cudaGetSymbolAddress((void**)&kvz,  g_kvz);

    __nv_bfloat16 *mhi, *mlo, *hhi, *hlo, *thi, *tlo;
    __nv_bfloat16 *wqh, *wql, *wkh, *wkl, *wvh, *wvl, *wmh, *wml, *w1h, *w1l, *w2h, *w2l;
    cudaGetSymbolAddress((void**)&mhi, g_mhi);  cudaGetSymbolAddress((void**)&mlo, g_mlo);
    cudaGetSymbolAddress((void**)&hhi, g_hhi);  cudaGetSymbolAddress((void**)&hlo, g_hlo);
    cudaGetSymbolAddress((void**)&thi, g_thi);  cudaGetSymbolAddress((void**)&tlo, g_tlo);
    cudaGetSymbolAddress((void**)&wqh, g_wqh);  cudaGetSymbolAddress((void**)&wql, g_wql);
    cudaGetSymbolAddress((void**)&wkh, g_wkh);  cudaGetSymbolAddress((void**)&wkl, g_wkl);
    cudaGetSymbolAddress((void**)&wvh, g_wvh);  cudaGetSymbolAddress((void**)&wvl, g_wvl);
    cudaGetSymbolAddress((void**)&wmh, g_wmh);  cudaGetSymbolAddress((void**)&wml, g_wml);
    cudaGetSymbolAddress((void**)&w1h, g_w1h);  cudaGetSymbolAddress((void**)&w1l, g_w1l);
    cudaGetSymbolAddress((void**)&w2h, g_w2h);  cudaGetSymbolAddress((void**)&w2l, g_w2l);

    EncFn enc = nullptr;
    {
        void* fp = nullptr;
#if CUDART_VERSION >= 12050
        cudaDriverEntryPointQueryResult qr;
        cudaGetDriverEntryPoint("cuTensorMapEncodeTiled", &fp, cudaEnableDefault, &qr);
#else
        cudaGetDriverEntryPoint("cuTensorMapEncodeTiled", &fp, cudaEnableDefault);
#endif
        enc = (EncFn)fp;
    }
    auto mk = [&](void* ptr, uint64_t k_elems, uint64_t rows, uint32_t boxrows) {
        CUtensorMap m{};
        cuuint64_t dims[2] = {k_elems, rows};
        cuuint64_t strides[1] = {k_elems * 2};
        cuuint32_t box[2] = {64, boxrows};
        cuuint32_t es[2] = {1, 1};
        enc(&m, CU_TENSOR_MAP_DATA_TYPE_BFLOAT16, 2, ptr, dims, strides, box, es,
            CU_TENSOR_MAP_INTERLEAVE_NONE, CU_TENSOR_MAP_SWIZZLE_128B,
            CU_TENSOR_MAP_L2_PROMOTION_L2_128B, CU_TENSOR_MAP_FLOAT_OOB_FILL_NONE);
        return m;
    };
    CUtensorMap tm_mhi = mk(mhi, 256, ROWS, 128), tm_mlo = mk(mlo, 256, ROWS, 128);
    CUtensorMap tm_hhi = mk(hhi, 512, ROWS, 128), tm_hlo = mk(hlo, 512, ROWS, 128);
    CUtensorMap tm_thi = mk(thi, 512, ROWS, 128), tm_tlo = mk(tlo, 512, ROWS, 128);
    CUtensorMap tm_wqh = mk(wqh, 256, 256, 256), tm_wql = mk(wql, 256, 256, 256);
    CUtensorMap tm_wkh = mk(wkh, 256, 256, 256), tm_wkl = mk(wkl, 256, 256, 256);
    CUtensorMap tm_wvh = mk(wvh, 256, 256, 256), tm_wvl = mk(wvl, 256, 256, 256);
    CUtensorMap tm_wmh = mk(wmh, 256, 256, 256), tm_wml = mk(wml, 256, 256, 256);
    CUtensorMap tm_w1h = mk(w1h, 512, 512, 256), tm_w1l = mk(w1l, 512, 512, 256);
    CUtensorMap tm_w2h = mk(w2h, 512, 256, 256), tm_w2l = mk(w2l, 512, 256, 256);

    cudaFuncSetAttribute(tc_gemm<0>, cudaFuncAttributeMaxDynamicSharedMemorySize, SMEM_DYN);
    cudaFuncSetAttribute(tc_gemm<1>, cudaFuncAttributeMaxDynamicSharedMemorySize, SMEM_DYN);
    cudaFuncSetAttribute(tc_gemm<2>, cudaFuncAttributeMaxDynamicSharedMemorySize, SMEM_DYN);
    cudaFuncSetAttribute(tc_gemm<3>, cudaFuncAttributeMaxDynamicSharedMemorySize, SMEM_DYN);
    const int ATTN_SMEM = (H*DH*DH + H*DH + ATOK*256 + ATOK*H) * 4;
    cudaFuncSetAttribute(attn_out<0>,  cudaFuncAttributeMaxDynamicSharedMemorySize, ATTN_SMEM);
    cudaFuncSetAttribute(attn_out<21>, cudaFuncAttributeMaxDynamicSharedMemorySize, ATTN_SMEM);

    dim3 thr(256);

    wconv_all<<<2560, thr>>>(Wq, Wk, Wv, Wm, W1, W2);

    aconv<<<ROWS*D/4/256, thr>>>((const float4*)x, (__nv_bfloat162*)mhi, (__nv_bfloat162*)mlo, ROWS*D/4);
    tc_gemm<0><<<dim3(1, ROWS/BM), thr, SMEM_DYN>>>(tm_mhi, tm_mlo, tm_wqh, tm_wql,
            mhi, mlo, wqh, wql, q, nullptr, nullptr, nullptr, nullptr, D, D, 0);
    aconv<<<ROWS*D/4/256, thr>>>((const float4*)src, (__nv_bfloat162*)mhi, (__nv_bfloat162*)mlo, ROWS*D/4);
    tc_gemm<0><<<dim3(1, ROWS/BM), thr, SMEM_DYN>>>(tm_mhi, tm_mlo, tm_wkh, tm_wkl,
            mhi, mlo, wkh, wkl, k, nullptr, nullptr, nullptr, nullptr, D, D, 0);
    tc_gemm<0><<<dim3(1, ROWS/BM), thr, SMEM_DYN>>>(tm_mhi, tm_mlo, tm_wvh, tm_wvl,
            mhi, mlo, wvh, wvl, v, nullptr, nullptr, nullptr, nullptr, D, D, 0);

    prep_base<<<ROWS*64/256, thr>>>((const float4*)x, (float4*)xmid, hhi, hlo);

    auto block = [&](int mode, float* accbuf) {
        const float *qq = q, *kk = k, *vv = v;
        if (mode == 13) {
            perm13<<<dim3(ROWS/8, 1, 3), thr>>>(q, k, v, qp, kp, vp);
            qq = qp; kk = kp; vv = vp;
        } else if (mode == 32) {
            perm32<<<dim3(150, BS, 3), thr>>>(q, k, v, qp, kp, vp);
            qq = qp; kk = kp; vv = vp;
        }
        cudaMemsetAsync(kvz, 0, (size_t)(BS*H*DH*DH + BS*H*DH) * sizeof(float));
        if (mode == 21) {
            kv_reduce<21><<<dim3(BS*H, KVSPLIT), thr>>>(k, v);
            attn_out<21><<<dim3(LL/ATOK, BS), thr, ATTN_SMEM>>>(q, mhi, mlo);
        } else {
            kv_reduce<0><<<dim3(BS*H, KVSPLIT), thr>>>(kk, vv);
            attn_out<0><<<dim3(LL/ATOK, BS), thr, ATTN_SMEM>>>(qq, mhi, mlo);
        }
        tc_gemm<2><<<dim3(1, ROWS/BM), thr, SMEM_DYN>>>(tm_mhi, tm_mlo, tm_wmh, tm_wml,
                mhi, mlo, wmh, wml, nullptr, hhi, hlo, g1, b1, D, 2*D, D);
        tc_gemm<1><<<dim3(2, ROWS/BM), thr, SMEM_DYN>>>(tm_hhi, tm_hlo, tm_w1h, tm_w1l,
                hhi, hlo, w1h, w1l, nullptr, thi, tlo, nullptr, nullptr, 2*D, 2*D, 0);
        tc_gemm<3><<<dim3(1, ROWS/BM), thr, SMEM_DYN>>>(tm_thi, tm_tlo, tm_w2h, tm_w2l,
                thi, tlo, w2h, w2l, accbuf, nullptr, nullptr, g2, b2, 2*D, D, 0);
    };

    block(0,  xmid);
    block(13, xmid);
    prep_base<<<ROWS*64/256, thr>>>((const float4*)xmid, (float4*)out, hhi, hlo);
    block(21, out);
    block(32, out);
}

// round 9
// speedup vs baseline: 2.1328x; 1.3964x over previous
#include <cuda_runtime.h>
#include <cuda.h>
#include <cuda_bf16.h>
#include <math.h>
#include <stdint.h>

#if defined(__CUDA_ARCH__) && defined(__CUDA_ARCH_FEAT_SM103_ALL)
#define HAS_TCGEN05 1
#else
#define HAS_TCGEN05 0
#endif

#define BS 8
#define LL 4800
#define D 256
#define H 8
#define DH 32
#define ROWS (BS*LL)   // 38400
#define BSTRIDE (LL*D)

#define BM 128
#define BN 256
#define BK 64
#define A_HI 0
#define A_LO 16384
#define B_HI 32768
#define B_LO 65536
#define STAGE_BYTES 98304
#define SMEM_DYN (2*STAGE_BYTES + 1024)

#define ATOK 32
#define KVN (BS*H*DH*DH + BS*H*DH)

// ---------------- scratch (device globals) ----------------
__device__ float g_q   [BS*LL*D];
__device__ float g_k   [BS*LL*D];
__device__ float g_v   [BS*LL*D];
__device__ float g_qp  [BS*LL*D];
__device__ float g_kp  [BS*LL*D];
__device__ float g_vp  [BS*LL*D];
__device__ float g_xmid[BS*LL*D];
__device__ float g_kvzA[KVN];
__device__ float g_kvzB[KVN];

// set A
__device__ __align__(1024) __nv_bfloat16 g_mhiA[ROWS*D],   g_mloA[ROWS*D];
__device__ __align__(1024) __nv_bfloat16 g_hhiA[ROWS*2*D], g_hloA[ROWS*2*D];
__device__ __align__(1024) __nv_bfloat16 g_thiA[ROWS*2*D], g_tloA[ROWS*2*D];
// set B
__device__ __align__(1024) __nv_bfloat16 g_mhiB[ROWS*D],   g_mloB[ROWS*D];
__device__ __align__(1024) __nv_bfloat16 g_hhiB[ROWS*2*D], g_hloB[ROWS*2*D];
__device__ __align__(1024) __nv_bfloat16 g_thiB[ROWS*2*D], g_tloB[ROWS*2*D];

__device__ __align__(1024) __nv_bfloat16 g_wqh[D*D],     g_wql[D*D];
__device__ __align__(1024) __nv_bfloat16 g_wkh[D*D],     g_wkl[D*D];
__device__ __align__(1024) __nv_bfloat16 g_wvh[D*D],     g_wvl[D*D];
__device__ __align__(1024) __nv_bfloat16 g_wmh[D*D],     g_wml[D*D];
__device__ __align__(1024) __nv_bfloat16 g_w1h[2*D*2*D], g_w1l[2*D*2*D];
__device__ __align__(1024) __nv_bfloat16 g_w2h[D*2*D],   g_w2l[D*2*D];

// ---------------- helpers ----------------
__device__ __forceinline__ float phi(float x) { return x > 0.f ? x + 1.f : __expf(x); }
__device__ __forceinline__ uint32_t smem_u32(const void* p) {
    uint32_t a;
    asm("{ .reg .u64 t; cvta.to.shared.u64 t, %1; cvt.u32.u64 %0, t; }" : "=r"(a) : "l"(p));
    return a;
}
__device__ __forceinline__ void split_store(__nv_bfloat16* hi, __nv_bfloat16* lo,
                                            size_t idx, float v) {
    __nv_bfloat16 h = __float2bfloat16(v);
    hi[idx] = h;
    lo[idx] = __float2bfloat16(v - __bfloat162float(h));
}

template<int MODE>
__device__ __forceinline__ int map_off(int l, int c) {
    if (MODE == 21) {
        int F = l * 256 + c;
        int h0 = F / 153600;
        int rem = F - h0 * 153600;
        int l0 = rem >> 5;
        return l0 * 256 + h0 * 32 + (rem & 31);
    }
    return l * 256 + c;
}

#if HAS_TCGEN05
__device__ __forceinline__ void mbar_init(uint32_t a, uint32_t cnt) {
    asm volatile("mbarrier.init.shared.b64 [%0], %1;" :: "r"(a), "r"(cnt) : "memory");
}
__device__ __forceinline__ void mbar_wait(uint32_t a, uint32_t parity) {
    asm volatile(
        "{\n\t.reg .pred P;\n"
        "W_%=:\n\t"
        "mbarrier.try_wait.parity.acquire.cta.shared::cta.b64 P, [%0], %1, 0x989680;\n\t"
        "@!P bra W_%=;\n\t}"
        :: "r"(a), "r"(parity) : "memory");
}
__device__ __forceinline__ void mbar_expect_tx(uint32_t a, uint32_t bytes) {
    asm volatile("mbarrier.arrive.expect_tx.shared.b64 _, [%0], %1;"
                 :: "r"(a), "r"(bytes) : "memory");
}
__device__ __forceinline__ void tma2d(uint32_t smem, const CUtensorMap* map,
                                      int x, int y, uint32_t mbar) {
    asm volatile(
        "cp.async.bulk.tensor.2d.shared::cta.global.tile.mbarrier::complete_tx::bytes "
        "[%0], [%1, {%2, %3}], [%4];"
        :: "r"(smem), "l"(map), "r"(x), "r"(y), "r"(mbar) : "memory");
}
__device__ __forceinline__ uint64_t make_desc(uint32_t addr) {
    const uint64_t base = (uint64_t(2) << 61) | (uint64_t(1) << 46)
                        | (uint64_t(64) << 32) | (uint64_t(1) << 16);
    return base | ((uint64_t)(addr >> 4) & 0x3FFF);
}
__device__ __forceinline__ void mma_f16_ss(uint32_t d, uint64_t a, uint64_t b,
                                           uint32_t idesc, uint32_t en) {
    asm volatile(
        "{\n\t.reg .pred p;\n\tsetp.ne.u32 p, %5, 0;\n\t"
        "tcgen05.mma.cta_group::1.kind::f16 [%0], %1, %2, %3, {%4, %4, %4, %4}, p;\n\t}"
        :: "r"(d), "l"(a), "l"(b), "r"(idesc), "r"(0u), "r"(en) : "memory");
}
__device__ __forceinline__ void tc_commit(uint32_t mbar) {
    asm volatile(
        "tcgen05.commit.cta_group::1.mbarrier::arrive::one.shared::cluster.b64 [%0];"
        :: "r"(mbar) : "memory");
}
__device__ __forceinline__ void ldtm32(uint32_t* r, uint32_t addr) {
    asm volatile(
        "tcgen05.ld.sync.aligned.32x32b.x32.b32 "
        "{%0, %1, %2, %3, %4, %5, %6, %7, "
        " %8, %9, %10, %11, %12, %13, %14, %15, "
        " %16, %17, %18, %19, %20, %21, %22, %23, "
        " %24, %25, %26, %27, %28, %29, %30, %31}, [%32];"
        : "=r"(r[0]),  "=r"(r[1]),  "=r"(r[2]),  "=r"(r[3]),
          "=r"(r[4]),  "=r"(r[5]),  "=r"(r[6]),  "=r"(r[7]),
          "=r"(r[8]),  "=r"(r[9]),  "=r"(r[10]), "=r"(r[11]),
          "=r"(r[12]), "=r"(r[13]), "=r"(r[14]), "=r"(r[15]),
          "=r"(r[16]), "=r"(r[17]), "=r"(r[18]), "=r"(r[19]),
          "=r"(r[20]), "=r"(r[21]), "=r"(r[22]), "=r"(r[23]),
          "=r"(r[24]), "=r"(r[25]), "=r"(r[26]), "=r"(r[27]),
          "=r"(r[28]), "=r"(r[29]), "=r"(r[30]), "=r"(r[31])
        : "r"(addr));
    asm volatile("tcgen05.wait::ld.sync.aligned;" ::: "memory");
}
#endif

// ---------------- convert kernels ----------------
__global__ void __launch_bounds__(256) aconv(const float4* __restrict__ a,
                                             __nv_bfloat162* __restrict__ hi,
                                             __nv_bfloat162* __restrict__ lo, int n4) {
    int i = blockIdx.x * 256 + threadIdx.x;
    if (i >= n4) return;
    float4 v = a[i];
    __nv_bfloat16 h0 = __float2bfloat16(v.x), h1 = __float2bfloat16(v.y);
    __nv_bfloat16 h2 = __float2bfloat16(v.z), h3 = __float2bfloat16(v.w);
    hi[2*i]   = __halves2bfloat162(h0, h1);
    hi[2*i+1] = __halves2bfloat162(h2, h3);
    lo[2*i]   = __halves2bfloat162(__float2bfloat16(v.x - __bfloat162float(h0)),
                                   __float2bfloat16(v.y - __bfloat162float(h1)));
    lo[2*i+1] = __halves2bfloat162(__float2bfloat16(v.z - __bfloat162float(h2)),
                                   __float2bfloat16(v.w - __bfloat162float(h3)));
}

__global__ void __launch_bounds__(256) wconv_all(
        const float* __restrict__ Wq, const float* __restrict__ Wk,
        const float* __restrict__ Wv, const float* __restrict__ Wm,
        const float* __restrict__ W1, const float* __restrict__ W2) {
    int i = blockIdx.x * 256 + threadIdx.x;
    if (i >= 655360) return;
    const float* W; __nv_bfloat16 *hi, *lo; int K, N, li = i;
    if (li < 65536)                { W = Wq; hi = g_wqh; lo = g_wql; K = 256; N = 256; }
    else if ((li -= 65536) < 65536){ W = Wk; hi = g_wkh; lo = g_wkl; K = 256; N = 256; }
    else if ((li -= 65536) < 65536){ W = Wv; hi = g_wvh; lo = g_wvl; K = 256; N = 256; }
    else if ((li -= 65536) < 65536){ W = Wm; hi = g_wmh; lo = g_wml; K = 256; N = 256; }
    else if ((li -= 65536) < 262144){ W = W1; hi = g_w1h; lo = g_w1l; K = 512; N = 512; }
    else { li -= 262144;             W = W2; hi = g_w2h; lo = g_w2l; K = 512; N = 256; }
    int n = li / K, k = li % K;
    float v = W[(size_t)k * N + n];
    __nv_bfloat16 h = __float2bfloat16(v);
    hi[li] = h;
    lo[li] = __float2bfloat16(v - __bfloat162float(h));
}

// xb -> copy to dst + hcat base halves of BOTH sets (pitch 512)
__global__ void __launch_bounds__(256) prep_base2(const float4* __restrict__ xb,
                                                  float4* __restrict__ dst,
                                                  __nv_bfloat16* __restrict__ hhiA,
                                                  __nv_bfloat16* __restrict__ hloA,
                                                  __nv_bfloat16* __restrict__ hhiB,
                                                  __nv_bfloat16* __restrict__ hloB) {
    int i = blockIdx.x * 256 + threadIdx.x;
    if (i >= ROWS * 64) return;
    float4 v = xb[i];
    dst[i] = v;
    int row = i >> 6, j = i & 63;
    size_t o = (size_t)row * 512 + j * 4;
    float vv[4] = {v.x, v.y, v.z, v.w};
    #pragma unroll
    for (int e = 0; e < 4; e++) {
        __nv_bfloat16 h = __float2bfloat16(vv[e]);
        __nv_bfloat16 l = __float2bfloat16(vv[e] - __bfloat162float(h));
        hhiA[o + e] = h; hloA[o + e] = l;
        hhiB[o + e] = h; hloB[o + e] = l;
    }
}

// ---------------- tcgen05 GEMM with TMA mainloop (R5 pipeline) ----------------
// EPI 0: fp32 -> Cf ; EPI 1: relu -> bf16 hi/lo ; EPI 2: LN -> bf16 hi/lo at coff ;
// EPI 3: atomicAdd(Cf, 0.5*LN)
template<int EPI>
__global__ void __launch_bounds__(256, 1) tc_gemm(
        const __grid_constant__ CUtensorMap mAh, const __grid_constant__ CUtensorMap mAl,
        const __grid_constant__ CUtensorMap mBh, const __grid_constant__ CUtensorMap mBl,
        const __nv_bfloat16* __restrict__ Ahi, const __nv_bfloat16* __restrict__ Alo,
        const __nv_bfloat16* __restrict__ Bhi, const __nv_bfloat16* __restrict__ Blo,
        float* __restrict__ Cf,
        __nv_bfloat16* __restrict__ Chi, __nv_bfloat16* __restrict__ Clo,
        const float* __restrict__ Gw, const float* __restrict__ Bw,
        int K, int ldc, int coff) {
#if HAS_TCGEN05
    extern __shared__ char dsm_raw[];
    char* sbase = (char*)(((uintptr_t)dsm_raw + 1023) & ~(uintptr_t)1023);
    __shared__ uint32_t s_tmem;
    __shared__ __align__(8) unsigned long long s_mbar[4];
    const uint32_t mb = smem_u32(s_mbar);
    const int t = threadIdx.x, wid = t >> 5, lane = t & 31;

    if (wid == 0) {
        asm volatile("tcgen05.alloc.cta_group::1.sync.aligned.shared::cta.b32 [%0], %1;"
                     :: "r"(smem_u32(&s_tmem)), "r"(256u) : "memory");
        asm volatile("tcgen05.relinquish_alloc_permit.cta_group::1.sync.aligned;");
    }
    if (t == 0) {
        mbar_init(mb, 1); mbar_init(mb + 8, 1);
        mbar_init(mb + 16, 1); mbar_init(mb + 24, 1);
    }
    __syncthreads();
    const uint32_t tmem = s_tmem;

    const int bm = blockIdx.y * BM, bn = blockIdx.x * BN;
    const int NC = K >> 6;
    const uint32_t idesc = (1u << 4) | (1u << 7) | (1u << 10)
                         | ((BN / 8) << 17) | ((BM / 16) << 24);
    const uint32_t sb32 = smem_u32(sbase);

    if (t == 0) {
        mbar_expect_tx(mb, STAGE_BYTES);
        tma2d(sb32 + A_HI, &mAh, 0, bm, mb);
        tma2d(sb32 + A_LO, &mAl, 0, bm, mb);
        tma2d(sb32 + B_HI, &mBh, 0, bn, mb);
        tma2d(sb32 + B_LO, &mBl, 0, bn, mb);
        if (NC > 1) {
            uint32_t st = sb32 + STAGE_BYTES;
            mbar_expect_tx(mb + 8, STAGE_BYTES);
            tma2d(st + A_HI, &mAh, BK, bm, mb + 8);
            tma2d(st + A_LO, &mAl, BK, bm, mb + 8);
            tma2d(st + B_HI, &mBh, BK, bn, mb + 8);
            tma2d(st + B_LO, &mBl, BK, bn, mb + 8);
        }
        int fph[2] = {0, 0}, mph[2] = {0, 0}, pend[2] = {0, 0};
        for (int c = 0; c < NC; c++) {
            const int s = c & 1;
            mbar_wait(mb + s * 8, fph[s]); fph[s] ^= 1;
            uint32_t st = sb32 + s * STAGE_BYTES;
            uint64_t dAh = make_desc(st + A_HI), dAl = make_desc(st + A_LO);
            uint64_t dBh = make_desc(st + B_HI), dBl = make_desc(st + B_LO);
            #pragma unroll
            for (int kk2 = 0; kk2 < 4; kk2++) {
                mma_f16_ss(tmem, dAh + kk2 * 2, dBh + kk2 * 2, idesc, (c > 0) || (kk2 > 0));
                mma_f16_ss(tmem, dAh + kk2 * 2, dBl + kk2 * 2, idesc, 1u);
                mma_f16_ss(tmem, dAl + kk2 * 2, dBh + kk2 * 2, idesc, 1u);
            }
            tc_commit(mb + 16 + s * 8);
            pend[s] = 1;
            if (c + 2 < NC) {
                mbar_wait(mb + 16 + s * 8, mph[s]); mph[s] ^= 1; pend[s] = 0;
                int k0 = (c + 2) * BK;
                mbar_expect_tx(mb + s * 8, STAGE_BYTES);
                tma2d(st + A_HI, &mAh, k0, bm, mb + s * 8);
                tma2d(st + A_LO, &mAl, k0, bm, mb + s * 8);
                tma2d(st + B_HI, &mBh, k0, bn, mb + s * 8);
                tma2d(st + B_LO, &mBl, k0, bn, mb + s * 8);
            }
        }
        if (pend[0]) mbar_wait(mb + 16, mph[0]);
        if (pend[1]) mbar_wait(mb + 24, mph[1]);
    }
    __syncthreads();
    asm volatile("tcgen05.fence::after_thread_sync;" ::: "memory");

    float (*tile)[33] = (float(*)[33])sbase;
    float mean = 0.f, rstd = 0.f;
    if (EPI >= 2 && wid < 4) {
        float s = 0.f, s2 = 0.f;
        #pragma unroll
        for (int ch = 0; ch < 8; ch++) {
            uint32_t r[32];
            ldtm32(r, tmem + ch * 32);
            #pragma unroll
            for (int j = 0; j < 32; j++) {
                float v = __uint_as_float(r[j]);
                s += v; s2 += v * v;
            }
        }
        mean = s * (1.f / 256.f);
        float var = fmaf(-mean, mean, s2 * (1.f / 256.f));
        rstd = rsqrtf(var + 1e-5f);
    }
    #pragma unroll
    for (int ch = 0; ch < 8; ch++) {
        if (wid < 4) {
            uint32_t r[32];
            ldtm32(r, tmem + ch * 32);
            int rloc = wid * 32 + lane;
            #pragma unroll
            for (int j = 0; j < 32; j++) {
                float v = __uint_as_float(r[j]);
                if (EPI == 1) v = fmaxf(v, 0.f);
                if (EPI >= 2) {
                    int col = ch * 32 + j;
                    v = (v - mean) * rstd * Gw[col] + Bw[col];
                    if (EPI == 3) v *= 0.5f;
                }
                tile[rloc][j] = v;
            }
        }
        __syncthreads();
        #pragma unroll
        for (int i = 0; i < 16; i++) {
            int idx = i * 256 + t;
            int rr = idx >> 5, cc = idx & 31;
            float v = tile[rr][cc];
            size_t ro = (size_t)(bm + rr) * ldc + bn + coff + ch * 32 + cc;
            if (EPI == 0)       Cf[ro] = v;
            else if (EPI == 3)  atomicAdd(Cf + ro, v);
            else                split_store(Chi, Clo, ro, v);
        }
        __syncthreads();
    }
    if (wid == 0)
        asm volatile("tcgen05.dealloc.cta_group::1.sync.aligned.b32 %0, %1;"
                     :: "r"(tmem), "r"(256u));
#else
    // compile-only fallback (never runs on GB300)
    const int bm = blockIdx.y * BM, bn = blockIdx.x * BN;
    const int t = threadIdx.x;
    if (t < BM) {
        int row = bm + t;
        float vals[BN];
        for (int c = 0; c < BN; c++) {
            const __nv_bfloat16* ah = Ahi + (size_t)row * K;
            const __nv_bfloat16* al = Alo + (size_t)row * K;
            const __nv_bfloat16* bh = Bhi + (size_t)(bn + c) * K;
            const __nv_bfloat16* bl = Blo + (size_t)(bn + c) * K;
            float acc = 0.f;
            for (int kk = 0; kk < K; kk++)
                acc += (__bfloat162float(ah[kk]) + __bfloat162float(al[kk])) *
                       (__bfloat162float(bh[kk]) + __bfloat162float(bl[kk]));
            vals[c] = acc;
        }
        float mean = 0.f, rstd = 1.f;
        if (EPI >= 2) {
            float s = 0.f, s2 = 0.f;
            for (int c = 0; c < BN; c++) { s += vals[c]; s2 += vals[c] * vals[c]; }
            mean = s / BN;
            rstd = rsqrtf(s2 / BN - mean * mean + 1e-5f);
        }
        for (int c = 0; c < BN; c++) {
            float v = vals[c];
            if (EPI == 1) v = fmaxf(v, 0.f);
            if (EPI >= 2) { v = (v - mean) * rstd * Gw[c] + Bw[c]; if (EPI == 3) v *= 0.5f; }
            size_t ro = (size_t)row * ldc + bn + coff + c;
            if (EPI == 0)      Cf[ro] = v;
            else if (EPI == 3) atomicAdd(Cf + ro, v);
            else               split_store(Chi, Clo, ro, v);
        }
    }
#endif
}

// ---------------- coalesced permutes (modes 13 / 32) ----------------
__global__ void __launch_bounds__(256) perm13(const float* q, const float* k, const float* v,
                                              float* qd, float* kd, float* vd) {
    __shared__ float s[8][256];
    const float* S = blockIdx.z == 0 ? q : (blockIdx.z == 1 ? k : v);
    float* Dd = blockIdx.z == 0 ? qd : (blockIdx.z == 1 ? kd : vd);
    size_t rowbase = (size_t)blockIdx.x * 8;
    int t = threadIdx.x;
    #pragma unroll
    for (int i = 0; i < 8; i++) s[i][t] = S[(rowbase + i) * 256 + t];
    __syncthreads();
    int c0 = (t & 7) * 32 + (t >> 3);
    #pragma unroll
    for (int i = 0; i < 8; i++) Dd[(rowbase + i) * 256 + t] = s[i][c0];
}

__global__ void __launch_bounds__(256) perm32(const float* q, const float* k, const float* v,
                                              float* qd, float* kd, float* vd) {
    __shared__ float sm[32][33];
    const float* S = blockIdx.z == 0 ? q : (blockIdx.z == 1 ? k : v);
    float* Dd = blockIdx.z == 0 ? qd : (blockIdx.z == 1 ? kd : vd);
    int b = blockIdx.y;
    int l0b = blockIdx.x * 32;
    size_t bo = (size_t)b * BSTRIDE;
    int wr = threadIdx.x >> 5, lane = threadIdx.x & 31;
    for (int h0 = 0; h0 < H; h0++) {
        #pragma unroll
        for (int it = 0; it < 4; it++) {
            int row = wr + it * 8;
            sm[row][lane] = S[bo + (size_t)(l0b + row) * 256 + h0 * 32 + lane];
        }
        __syncthreads();
        #pragma unroll
        for (int it = 0; it < 4; it++) {
            int d0 = wr + it * 8;
            Dd[bo + (size_t)d0 * 38400 + h0 * 4800 + l0b + lane] = sm[lane][d0];
        }
        __syncthreads();
    }
}

// ---------------- KV reduce ----------------
#define KVSPLIT 10
#define KVCHUNK (LL/KVSPLIT)
template<int MODE>
__global__ void __launch_bounds__(256) kv_reduce(const float* __restrict__ k,
                                                 const float* __restrict__ v,
                                                 float* __restrict__ kvz) {
    int b = blockIdx.x >> 3, h = blockIdx.x & 7;
    int sbeg = blockIdx.y * KVCHUNK;
    const float* kb = k + (size_t)b * BSTRIDE;
    const float* vb = v + (size_t)b * BSTRIDE;
    __shared__ float ks[8][32], vs[8][32];
    int t = threadIdx.x;
    int r = t >> 5, c = t & 31;
    float acc[4] = {0.f, 0.f, 0.f, 0.f};
    float ksacc = 0.f;
    for (int s0 = sbeg; s0 < sbeg + KVCHUNK; s0 += 8) {
        int off = map_off<MODE>(s0 + r, h * DH + c);
        ks[r][c] = phi(kb[off]);
        vs[r][c] = vb[off];
        __syncthreads();
        #pragma unroll
        for (int row = 0; row < 8; row++) {
            float ve = vs[row][c];
            #pragma unroll
            for (int jj = 0; jj < 4; jj++)
                acc[jj] += ks[row][r + jj * 8] * ve;
        }
        if (t < 32) {
            #pragma unroll
            for (int row = 0; row < 8; row++) ksacc += ks[row][t];
        }
        __syncthreads();
    }
    float* kvout = kvz + (size_t)(b * H + h) * DH * DH;
    #pragma unroll
    for (int jj = 0; jj < 4; jj++)
        atomicAdd(&kvout[(r + jj * 8) * DH + c], acc[jj]);
    if (t < 32) atomicAdd(&kvz[BS*H*DH*DH + (b * H + h) * DH + t], ksacc);
}

// ---------------- attention apply ----------------
template<int MODE>
__global__ void __launch_bounds__(256) attn_out(const float* __restrict__ q,
                                                const float* __restrict__ kvz,
                                                __nv_bfloat16* __restrict__ mhi,
                                                __nv_bfloat16* __restrict__ mlo) {
    extern __shared__ float as_[];
    float* sKV = as_;
    float* sKs = sKV + H * DH * DH;
    float (*sQ)[256] = (float(*)[256])(sKs + H * DH);
    float* sZ = (float*)(sQ + ATOK);
    int b  = blockIdx.y;
    int l0 = blockIdx.x * ATOK;
    int t = threadIdx.x;
    const float* kvb = kvz + (size_t)b * H * DH * DH;
    #pragma unroll
    for (int i = t; i < H * DH * DH; i += 256) sKV[i] = kvb[i];
    if (t < H * DH) sKs[t] = kvz[BS*H*DH*DH + b * H * DH + t];
    const float* qb = q + (size_t)b * BSTRIDE;
    #pragma unroll
    for (int i = 0; i < ATOK; i++) sQ[i][t] = phi(qb[map_off<MODE>(l0 + i, t)]);
    __syncthreads();
    {
        int tok = t >> 3, h = t & 7;
        float z = 0.f;
        #pragma unroll
        for (int d = 0; d < DH; d++) z += sQ[tok][h * DH + d] * sKs[h * DH + d];
        sZ[tok * H + h] = 1.f / (z + 1e-6f);
    }
    __syncthreads();
    int c = t, h = c >> 5, e = c & 31;
    float kvreg[DH];
    #pragma unroll
    for (int d = 0; d < DH; d++) kvreg[d] = sKV[(h * DH + d) * DH + e];
    size_t base = (size_t)b * BSTRIDE + (size_t)l0 * D;
    #pragma unroll 4
    for (int jj = 0; jj < ATOK; jj++) {
        float dot = 0.f;
        #pragma unroll
        for (int d = 0; d < DH; d++)
            dot += sQ[jj][h * DH + d] * kvreg[d];
        split_store(mhi, mlo, base + (size_t)jj * D + c, dot * sZ[jj * H + h]);
    }
}

// ---------------- host orchestration ----------------
typedef CUresult (*EncFn)(CUtensorMap*, CUtensorMapDataType, cuuint32_t, void*,
        const cuuint64_t*, const cuuint64_t*, const cuuint32_t*, const cuuint32_t*,
        CUtensorMapInterleave, CUtensorMapSwizzle, CUtensorMapL2promotion,
        CUtensorMapFloatOOBfill);

extern "C" void kernel_launch(void* const* d_in, const int* in_sizes, int n_in,
                              void* d_out, int out_size) {
    (void)in_sizes; (void)n_in; (void)out_size;
    const float* x   = (const float*)d_in[0];
    const float* src = (const float*)d_in[1];
    const float* Wq  = (const float*)d_in[2];
    const float* Wk  = (const float*)d_in[3];
    const float* Wv  = (const float*)d_in[4];
    const float* Wm  = (const float*)d_in[5];
    const float* W1  = (const float*)d_in[6];
    const float* W2  = (const float*)d_in[7];
    const float* g1  = (const float*)d_in[8];
    const float* b1  = (const float*)d_in[9];
    const float* g2  = (const float*)d_in[10];
    const float* b2  = (const float*)d_in[11];
    float* out = (float*)d_out;

    float *q, *k, *v, *qp, *kp, *vp, *xmid, *kvzA, *kvzB;
    cudaGetSymbolAddress((void**)&q,    g_q);
    cudaGetSymbolAddress((void**)&k,    g_k);
    cudaGetSymbolAddress((void**)&v,    g_v);
    cudaGetSymbolAddress((void**)&qp,   g_qp);
    cudaGetSymbolAddress((void**)&kp,   g_kp);
    cudaGetSymbolAddress((void**)&vp,   g_vp);
    cudaGetSymbolAddress((void**)&xmid, g_xmid);
    cudaGetSymbolAddress((void**)&kvzA, g_kvzA);
    cudaGetSymbolAddress((void**)&kvzB, g_kvzB);

    __nv_bfloat16 *mhiA, *mloA, *hhiA, *hloA, *thiA, *tloA;
    __nv_bfloat16 *mhiB, *mloB, *hhiB, *hloB, *thiB, *tloB;
    __nv_bfloat16 *wqh, *wql, *wkh, *wkl, *wvh, *wvl, *wmh, *wml, *w1h, *w1l, *w2h, *w2l;
    cudaGetSymbolAddress((void**)&mhiA, g_mhiA); cudaGetSymbolAddress((void**)&mloA, g_mloA);
    cudaGetSymbolAddress((void**)&hhiA, g_hhiA); cudaGetSymbolAddress((void**)&hloA, g_hloA);
    cudaGetSymbolAddress((void**)&thiA, g_thiA); cudaGetSymbolAddress((void**)&tloA, g_tloA);
    cudaGetSymbolAddress((void**)&mhiB, g_mhiB); cudaGetSymbolAddress((void**)&mloB, g_mloB);
    cudaGetSymbolAddress((void**)&hhiB, g_hhiB); cudaGetSymbolAddress((void**)&hloB, g_hloB);
    cudaGetSymbolAddress((void**)&thiB, g_thiB); cudaGetSymbolAddress((void**)&tloB, g_tloB);
    cudaGetSymbolAddress((void**)&wqh, g_wqh);  cudaGetSymbolAddress((void**)&wql, g_wql);
    cudaGetSymbolAddress((void**)&wkh, g_wkh);  cudaGetSymbolAddress((void**)&wkl, g_wkl);
    cudaGetSymbolAddress((void**)&wvh, g_wvh);  cudaGetSymbolAddress((void**)&wvl, g_wvl);
    cudaGetSymbolAddress((void**)&wmh, g_wmh);  cudaGetSymbolAddress((void**)&wml, g_wml);
    cudaGetSymbolAddress((void**)&w1h, g_w1h);  cudaGetSymbolAddress((void**)&w1l, g_w1l);
    cudaGetSymbolAddress((void**)&w2h, g_w2h);  cudaGetSymbolAddress((void**)&w2l, g_w2l);

    EncFn enc = nullptr;
    {
        void* fp = nullptr;
#if CUDART_VERSION >= 12050
        cudaDriverEntryPointQueryResult qr;
        cudaGetDriverEntryPoint("cuTensorMapEncodeTiled", &fp, cudaEnableDefault, &qr);
#else
        cudaGetDriverEntryPoint("cuTensorMapEncodeTiled", &fp, cudaEnableDefault);
#endif
        enc = (EncFn)fp;
    }
    auto mk = [&](void* ptr, uint64_t k_elems, uint64_t rows, uint32_t boxrows) {
        CUtensorMap m{};
        cuuint64_t dims[2] = {k_elems, rows};
        cuuint64_t strides[1] = {k_elems * 2};
        cuuint32_t box[2] = {64, boxrows};
        cuuint32_t es[2] = {1, 1};
        enc(&m, CU_TENSOR_MAP_DATA_TYPE_BFLOAT16, 2, ptr, dims, strides, box, es,
            CU_TENSOR_MAP_INTERLEAVE_NONE, CU_TENSOR_MAP_SWIZZLE_128B,
            CU_TENSOR_MAP_L2_PROMOTION_L2_128B, CU_TENSOR_MAP_FLOAT_OOB_FILL_NONE);
        return m;
    };
    CUtensorMap tm_mhiA = mk(mhiA, 256, ROWS, 128), tm_mloA = mk(mloA, 256, ROWS, 128);
    CUtensorMap tm_hhiA = mk(hhiA, 512, ROWS, 128), tm_hloA = mk(hloA, 512, ROWS, 128);
    CUtensorMap tm_thiA = mk(thiA, 512, ROWS, 128), tm_tloA = mk(tloA, 512, ROWS, 128);
    CUtensorMap tm_mhiB = mk(mhiB, 256, ROWS, 128), tm_mloB = mk(mloB, 256, ROWS, 128);
    CUtensorMap tm_hhiB = mk(hhiB, 512, ROWS, 128), tm_hloB = mk(hloB, 512, ROWS, 128);
    CUtensorMap tm_thiB = mk(thiB, 512, ROWS, 128), tm_tloB = mk(tloB, 512, ROWS, 128);
    CUtensorMap tm_wqh = mk(wqh, 256, 256, 256), tm_wql = mk(wql, 256, 256, 256);
    CUtensorMap tm_wkh = mk(wkh, 256, 256, 256), tm_wkl = mk(wkl, 256, 256, 256);
    CUtensorMap tm_wvh = mk(wvh, 256, 256, 256), tm_wvl = mk(wvl, 256, 256, 256);
    CUtensorMap tm_wmh = mk(wmh, 256, 256, 256), tm_wml = mk(wml, 256, 256, 256);
    CUtensorMap tm_w1h = mk(w1h, 512, 512, 256), tm_w1l = mk(w1l, 512, 512, 256);
    CUtensorMap tm_w2h = mk(w2h, 512, 256, 256), tm_w2l = mk(w2l, 512, 256, 256);

    cudaFuncSetAttribute(tc_gemm<0>, cudaFuncAttributeMaxDynamicSharedMemorySize, SMEM_DYN);
    cudaFuncSetAttribute(tc_gemm<1>, cudaFuncAttributeMaxDynamicSharedMemorySize, SMEM_DYN);
    cudaFuncSetAttribute(tc_gemm<2>, cudaFuncAttributeMaxDynamicSharedMemorySize, SMEM_DYN);
    cudaFuncSetAttribute(tc_gemm<3>, cudaFuncAttributeMaxDynamicSharedMemorySize, SMEM_DYN);
    const int ATTN_SMEM = (H*DH*DH + H*DH + ATOK*256 + ATOK*H) * 4;
    cudaFuncSetAttribute(attn_out<0>,  cudaFuncAttributeMaxDynamicSharedMemorySize, ATTN_SMEM);
    cudaFuncSetAttribute(attn_out<21>, cudaFuncAttributeMaxDynamicSharedMemorySize, ATTN_SMEM);

    // streams/events (created once; host-side only)
    static cudaStream_t s1 = nullptr, s2 = nullptr;
    static cudaEvent_t ev[10];
    if (!s1) {
        cudaStreamCreateWithFlags(&s1, cudaStreamNonBlocking);
        cudaStreamCreateWithFlags(&s2, cudaStreamNonBlocking);
        for (int i = 0; i < 10; i++)
            cudaEventCreateWithFlags(&ev[i], cudaEventDisableTiming);
    }
    cudaEvent_t evRoot = ev[0], evQ = ev[1], evKV = ev[2], evPB1 = ev[3],
                evB0 = ev[4], evB13 = ev[5], evPB2 = ev[6], evB21 = ev[7], evB32 = ev[8];

    dim3 thr(256);

    // block chain: attn + 3 GEMMs on stream st using scratch set S
    auto blockrun = [&](cudaStream_t st, int mode, float* accbuf,
                        __nv_bfloat16* Smhi, __nv_bfloat16* Smlo,
                        __nv_bfloat16* Shhi, __nv_bfloat16* Shlo,
                        __nv_bfloat16* Sthi, __nv_bfloat16* Stlo,
                        float* Skvz,
                        CUtensorMap& tmm_h, CUtensorMap& tmm_l,
                        CUtensorMap& tmh_h, CUtensorMap& tmh_l,
                        CUtensorMap& tmt_h, CUtensorMap& tmt_l) {
        const float *qq = q, *kk = k, *vv = v;
        if (mode == 13) {
            perm13<<<dim3(ROWS/8, 1, 3), thr, 0, st>>>(q, k, v, qp, kp, vp);
            qq = qp; kk = kp; vv = vp;
        } else if (mode == 32) {
            perm32<<<dim3(150, BS, 3), thr, 0, st>>>(q, k, v, qp, kp, vp);
            qq = qp; kk = kp; vv = vp;
        }
        cudaMemsetAsync(Skvz, 0, (size_t)KVN * sizeof(float), st);
        if (mode == 21) {
            kv_reduce<21><<<dim3(BS*H, KVSPLIT), thr, 0, st>>>(k, v, Skvz);
            attn_out<21><<<dim3(LL/ATOK, BS), thr, ATTN_SMEM, st>>>(q, Skvz, Smhi, Smlo);
        } else {
            kv_reduce<0><<<dim3(BS*H, KVSPLIT), thr, 0, st>>>(kk, vv, Skvz);
            attn_out<0><<<dim3(LL/ATOK, BS), thr, ATTN_SMEM, st>>>(qq, Skvz, Smhi, Smlo);
        }
        tc_gemm<2><<<dim3(1, ROWS/BM), thr, SMEM_DYN, st>>>(tmm_h, tmm_l, tm_wmh, tm_wml,
                Smhi, Smlo, wmh, wml, nullptr, Shhi, Shlo, g1, b1, D, 2*D, D);
        tc_gemm<1><<<dim3(2, ROWS/BM), thr, SMEM_DYN, st>>>(tmh_h, tmh_l, tm_w1h, tm_w1l,
                Shhi, Shlo, w1h, w1l, nullptr, Sthi, Stlo, nullptr, nullptr, 2*D, 2*D, 0);
        tc_gemm<3><<<dim3(1, ROWS/BM), thr, SMEM_DYN, st>>>(tmt_h, tmt_l, tm_w2h, tm_w2l,
                Sthi, Stlo, w2h, w2l, accbuf, nullptr, nullptr, g2, b2, 2*D, D, 0);
    };

    // ---- root: weight conversion ----
    wconv_all<<<2560, thr>>>(Wq, Wk, Wv, Wm, W1, W2);
    cudaEventRecord(evRoot, 0);
    cudaStreamWaitEvent(s1, evRoot, 0);
    cudaStreamWaitEvent(s2, evRoot, 0);

    // s1: x -> bf16 (set A), Wq
    aconv<<<ROWS*D/4/256, thr, 0, s1>>>((const float4*)x,
            (__nv_bfloat162*)mhiA, (__nv_bfloat162*)mloA, ROWS*D/4);
    tc_gemm<0><<<dim3(1, ROWS/BM), thr, SMEM_DYN, s1>>>(tm_mhiA, tm_mloA, tm_wqh, tm_wql,
            mhiA, mloA, wqh, wql, q, nullptr, nullptr, nullptr, nullptr, D, D, 0);
    cudaEventRecord(evQ, s1);

    // s2: src -> bf16 (set B), Wk, Wv
    aconv<<<ROWS*D/4/256, thr, 0, s2>>>((const float4*)src,
            (__nv_bfloat162*)mhiB, (__nv_bfloat162*)mloB, ROWS*D/4);
    tc_gemm<0><<<dim3(1, ROWS/BM), thr, SMEM_DYN, s2>>>(tm_mhiB, tm_mloB, tm_wkh, tm_wkl,
            mhiB, mloB, wkh, wkl, k, nullptr, nullptr, nullptr, nullptr, D, D, 0);
    tc_gemm<0><<<dim3(1, ROWS/BM), thr, SMEM_DYN, s2>>>(tm_mhiB, tm_mloB, tm_wvh, tm_wvl,
            mhiB, mloB, wvh, wvl, v, nullptr, nullptr, nullptr, nullptr, D, D, 0);
    cudaEventRecord(evKV, s2);

    // s0: xmid = x, hcat bases (both sets)
    prep_base2<<<ROWS*64/256, thr>>>((const float4*)x, (float4*)xmid, hhiA, hloA, hhiB, hloB);
    cudaEventRecord(evPB1, 0);

    // ---- phase 1: block 0 (s1, set A) || block 13 (s2, set B) ----
    cudaStreamWaitEvent(s1, evKV, 0);
    cudaStreamWaitEvent(s1, evPB1, 0);
    blockrun(s1, 0, xmid, mhiA, mloA, hhiA, hloA, thiA, tloA, kvzA,
             tm_mhiA, tm_mloA, tm_hhiA, tm_hloA, tm_thiA, tm_tloA);
    cudaEventRecord(evB0, s1);

    cudaStreamWaitEvent(s2, evQ, 0);
    cudaStreamWaitEvent(s2, evPB1, 0);
    blockrun(s2, 13, xmid, mhiB, mloB, hhiB, hloB, thiB, tloB, kvzB,
             tm_mhiB, tm_mloB, tm_hhiB, tm_hloB, tm_thiB, tm_tloB);
    cudaEventRecord(evB13, s2);

    // ---- join: out = xmid, hcat bases for phase 2 ----
    cudaStreamWaitEvent(0, evB0, 0);
    cudaStreamWaitEvent(0, evB13, 0);
    prep_base2<<<ROWS*64/256, thr>>>((const float4*)xmid, (float4*)out, hhiA, hloA, hhiB, hloB);
    cudaEventRecord(evPB2, 0);

    // ---- phase 2: block 21 (s1, set A) || block 32 (s2, set B) ----
    cudaStreamWaitEvent(s1, evPB2, 0);
    blockrun(s1, 21, out, mhiA, mloA, hhiA, hloA, thiA, tloA, kvzA,
             tm_mhiA, tm_mloA, tm_hhiA, tm_hloA, tm_thiA, tm_tloA);
    cudaEventRecord(evB21, s1);

    cudaStreamWaitEvent(s2, evPB2, 0);
    blockrun(s2, 32, out, mhiB, mloB, hhiB, hloB, thiB, tloB, kvzB,
             tm_mhiB, tm_mloB, tm_hhiB, tm_hloB, tm_thiB, tm_tloB);
    cudaEventRecord(evB32, s2);

    // ---- final join ----
    cudaStreamWaitEvent(0, evB21, 0);
    cudaStreamWaitEvent(0, evB32, 0);
}